// round 1
// baseline (speedup 1.0000x reference)
#include <cuda_runtime.h>

#define B_   64
#define ORD  2
#define S_   256
#define D_   256
#define H_   8
#define HD_  32
#define M_   (B_ * S_)   // 16384 rows per (i,j) projection GEMM

// Scratch (device globals — allocation-free per harness rules)
__device__ float g_xp[4][M_ * D_];   // [ij][(b*256+s)*256 + d]  projected x, 67 MB
__device__ float g_as[4][M_ * H_];   // per-source attention scores
__device__ float g_ad[4][M_ * H_];   // per-dest attention scores

// ---------------------------------------------------------------------------
// Kernel 1: projection GEMM  xp[ij] = x[:,i] @ Wp[i,j] + bp[i,j]
// grid (4, M/64, D/64), 256 threads, BM=BN=64, BK=16, 4x4 micro-tile
// ---------------------------------------------------------------------------
__global__ void proj_kernel(const float* __restrict__ x,
                            const float* __restrict__ Wp,
                            const float* __restrict__ bp) {
    const int ij = blockIdx.x;
    const int i  = ij >> 1;
    const int m0 = blockIdx.y * 64;
    const int n0 = blockIdx.z * 64;
    __shared__ __align__(16) float As[16][64];
    __shared__ __align__(16) float Bs[16][64];
    const int tid = threadIdx.x;
    const int tx = tid & 15, ty = tid >> 4;
    float acc[4][4] = {};
    const float* Wbase = Wp + ij * D_ * D_;

    for (int k0 = 0; k0 < D_; k0 += 16) {
        #pragma unroll
        for (int r = 0; r < 4; r++) {
            int idx = r * 256 + tid;
            int mm = idx >> 4, kk = idx & 15;
            int m = m0 + mm;
            int b = m >> 8, s = m & 255;
            As[kk][mm] = x[((b * ORD + i) * S_ + s) * D_ + k0 + kk];
        }
        #pragma unroll
        for (int r = 0; r < 4; r++) {
            int idx = r * 256 + tid;
            int nn = idx & 63, kk = idx >> 6;
            Bs[kk][nn] = Wbase[(k0 + kk) * D_ + n0 + nn];
        }
        __syncthreads();
        #pragma unroll
        for (int kk = 0; kk < 16; kk++) {
            float4 a4 = *(const float4*)&As[kk][ty * 4];
            float4 b4 = *(const float4*)&Bs[kk][tx * 4];
            float av[4] = {a4.x, a4.y, a4.z, a4.w};
            float bv[4] = {b4.x, b4.y, b4.z, b4.w};
            #pragma unroll
            for (int r = 0; r < 4; r++)
                #pragma unroll
                for (int c = 0; c < 4; c++)
                    acc[r][c] += av[r] * bv[c];
        }
        __syncthreads();
    }
    float4 bb = *(const float4*)&bp[ij * D_ + n0 + tx * 4];
    const float bv[4] = {bb.x, bb.y, bb.z, bb.w};
    #pragma unroll
    for (int r = 0; r < 4; r++) {
        int m = m0 + ty * 4 + r;
        float4 o;
        o.x = acc[r][0] + bv[0];
        o.y = acc[r][1] + bv[1];
        o.z = acc[r][2] + bv[2];
        o.w = acc[r][3] + bv[3];
        *(float4*)&g_xp[ij][m * D_ + n0 + tx * 4] = o;
    }
}

// ---------------------------------------------------------------------------
// Kernel 2: per-head src/dst scores  a_s[s,h] = xh[s,h,:]·att_src[h,:]
// grid (4, B), 256 threads = 8 warps (warp == head)
// ---------------------------------------------------------------------------
__global__ void score_kernel(const float* __restrict__ att_src,
                             const float* __restrict__ att_dst) {
    const int ij = blockIdx.x;
    const int b  = blockIdx.y;
    const int tid = threadIdx.x;
    const int h = tid >> 5, lane = tid & 31;
    const float asw = att_src[ij * 256 + h * HD_ + lane];
    const float adw = att_dst[ij * 256 + h * HD_ + lane];
    for (int s = 0; s < S_; s++) {
        float v = g_xp[ij][(b * S_ + s) * D_ + h * HD_ + lane];
        float ds = v * asw, dd = v * adw;
        #pragma unroll
        for (int o = 16; o > 0; o >>= 1) {
            ds += __shfl_xor_sync(0xffffffffu, ds, o);
            dd += __shfl_xor_sync(0xffffffffu, dd, o);
        }
        if (lane == 0) {
            g_as[ij][(b * S_ + s) * H_ + h] = ds;
            g_ad[ij][(b * S_ + s) * H_ + h] = dd;
        }
    }
}

// ---------------------------------------------------------------------------
// Kernel 3: fused mask -> leaky -> softmax(source axis) -> AV GEMM,
// accumulating both convs (j=0,1), adding projected-x residual + gbias.
// grid (8 t-tiles, ORD, B), 256 threads. Dynamic smem 70656 B:
//   W_sm[32][256] | Xp_sm[256][32] | as_sm[256] | ad_sm[2][32][8] | mask[2][256]
// ---------------------------------------------------------------------------
__global__ void attn_kernel(const int* __restrict__ A,
                            const float* __restrict__ gbias,
                            float* __restrict__ out) {
    const int t0 = blockIdx.x * 32;
    const int i  = blockIdx.y;
    const int b  = blockIdx.z;
    const int tid = threadIdx.x;
    const int lane = tid & 31, tg = tid >> 5;

    extern __shared__ __align__(16) float sm[];
    float* W_sm  = sm;                 // 8192 floats
    float* Xp_sm = sm + 8192;          // 8192 floats
    float* as_sm = sm + 16384;         // 256
    float* ad_sm = sm + 16640;         // 512
    unsigned* mask_sm = (unsigned*)(sm + 17152);  // 2*256 words

    // Edge masks for both convs, bit t' = edge(s, t0+t')
    {
        const int* Abase = A + ((long)(b * ORD + i) * S_) * S_ + t0;
        for (int k = 0; k < 32; k++) {
            int s = tg * 32 + k;
            int a = Abase[s * S_ + lane];
            unsigned m1 = __ballot_sync(0xffffffffu, (a == 2) | (a == 4));
            unsigned m2 = __ballot_sync(0xffffffffu, (a == 3) | (a == 4));
            if (lane == 0) { mask_sm[s] = m1; mask_sm[256 + s] = m2; }
        }
    }
    // a_dst for this t-tile, both convs
    for (int idx = tid; idx < 512; idx += 256) {
        int j = idx >> 8, rem = idx & 255;
        int tt = rem >> 3, h = rem & 7;
        ad_sm[idx] = g_ad[i * 2 + j][(b * S_ + t0 + tt) * H_ + h];
    }
    __syncthreads();

    for (int h = 0; h < H_; h++) {
        float acc0 = 0.f, acc1 = 0.f, acc2 = 0.f, acc3 = 0.f;
        for (int j = 0; j < 2; j++) {
            const int ij = i * 2 + j;
            __syncthreads();  // previous h/j use of smem done
            // stage Xp column block [256 s][32 d] and source scores
            const float* xpb = g_xp[ij] + (long)(b * S_) * D_ + h * HD_;
            for (int q = tid; q < 2048; q += 256) {
                int s = q >> 3, dq = q & 7;
                *(float4*)&Xp_sm[s * 32 + dq * 4] =
                    *(const float4*)&xpb[s * D_ + dq * 4];
            }
            as_sm[tid] = g_as[ij][(b * S_ + tid) * H_ + h];
            __syncthreads();

            // softmax weights: warp tg handles t' in {tg, tg+8, tg+16, tg+24}
            const unsigned* msk = mask_sm + j * 256;
            #pragma unroll
            for (int kk = 0; kk < 4; kk++) {
                int tp = tg + kk * 8;
                float adv = ad_sm[j * 256 + tp * 8 + h];
                float v[8];
                float mx = -1e30f;
                #pragma unroll
                for (int r = 0; r < 8; r++) {
                    int s = r * 32 + lane;
                    float a = as_sm[s] + adv;
                    a = a >= 0.f ? a : 0.2f * a;          // leaky_relu(0.2)
                    float vv = ((msk[s] >> tp) & 1u) ? a : 0.f;  // masked -> 0
                    v[r] = vv;
                    mx = fmaxf(mx, vv);
                }
                #pragma unroll
                for (int o = 16; o > 0; o >>= 1)
                    mx = fmaxf(mx, __shfl_xor_sync(0xffffffffu, mx, o));
                float sum = 0.f;
                #pragma unroll
                for (int r = 0; r < 8; r++) {
                    float e = __expf(v[r] - mx);
                    v[r] = e;
                    sum += e;
                }
                #pragma unroll
                for (int o = 16; o > 0; o >>= 1)
                    sum += __shfl_xor_sync(0xffffffffu, sum, o);
                float inv = 1.0f / sum;
                #pragma unroll
                for (int r = 0; r < 8; r++)
                    W_sm[tp * 256 + r * 32 + lane] = v[r] * inv;
            }
            __syncthreads();

            // AV GEMM: out[32 t][32 d] += W[32 t][256 s] * Xp[256 s][32 d]
            #pragma unroll 4
            for (int s4 = 0; s4 < 64; s4++) {
                float x0 = Xp_sm[(s4 * 4 + 0) * 32 + lane];
                float x1 = Xp_sm[(s4 * 4 + 1) * 32 + lane];
                float x2 = Xp_sm[(s4 * 4 + 2) * 32 + lane];
                float x3 = Xp_sm[(s4 * 4 + 3) * 32 + lane];
                float4 w0 = *(const float4*)&W_sm[(tg     ) * 256 + s4 * 4];
                float4 w1 = *(const float4*)&W_sm[(tg +  8) * 256 + s4 * 4];
                float4 w2 = *(const float4*)&W_sm[(tg + 16) * 256 + s4 * 4];
                float4 w3 = *(const float4*)&W_sm[(tg + 24) * 256 + s4 * 4];
                acc0 += w0.x * x0 + w0.y * x1 + w0.z * x2 + w0.w * x3;
                acc1 += w1.x * x0 + w1.y * x1 + w1.z * x2 + w1.w * x3;
                acc2 += w2.x * x0 + w2.y * x1 + w2.z * x2 + w2.w * x3;
                acc3 += w3.x * x0 + w3.y * x1 + w3.z * x2 + w3.w * x3;
            }
        }
        // h-slab epilogue: + xp residual (both convs) + gbias (both convs)
        int dfull = h * HD_ + lane;
        float gb = gbias[(i * 2 + 0) * D_ + dfull] + gbias[(i * 2 + 1) * D_ + dfull];
        const float* xp0 = g_xp[i * 2 + 0];
        const float* xp1 = g_xp[i * 2 + 1];
        float accs[4] = {acc0, acc1, acc2, acc3};
        #pragma unroll
        for (int kk = 0; kk < 4; kk++) {
            int t = t0 + tg + kk * 8;
            float val = accs[kk]
                      + xp0[(b * S_ + t) * D_ + dfull]
                      + xp1[(b * S_ + t) * D_ + dfull] + gb;
            out[((b * ORD + i) * S_ + t) * D_ + dfull] = val;
        }
    }
}

// ---------------------------------------------------------------------------
// Kernel 4: out = prelu(h + mean_over_order(h)), in place on d_out
// ---------------------------------------------------------------------------
__global__ void final_kernel(float* __restrict__ out,
                             const float* __restrict__ prelu_a) {
    int idx = blockIdx.x * 256 + threadIdx.x;    // over B*S*D
    if (idx >= B_ * S_ * D_) return;
    int d = idx & 255;
    int bs = idx >> 8;
    int b = bs >> 8, s = bs & 255;
    long i0 = ((long)(b * ORD + 0) * S_ + s) * D_ + d;
    long i1 = ((long)(b * ORD + 1) * S_ + s) * D_ + d;
    float h0 = out[i0];
    float h1 = out[i1];
    float m = 0.5f * (h0 + h1);
    float a = prelu_a[d];
    float o0 = h0 + m, o1 = h1 + m;
    o0 = o0 >= 0.f ? o0 : a * o0;
    o1 = o1 >= 0.f ? o1 : a * o1;
    out[i0] = o0;
    out[i1] = o1;
}

// ---------------------------------------------------------------------------
extern "C" void kernel_launch(void* const* d_in, const int* in_sizes, int n_in,
                              void* d_out, int out_size) {
    const float* x        = (const float*)d_in[0];
    const int*   A        = (const int*)  d_in[1];
    const float* Wp       = (const float*)d_in[2];
    const float* bp       = (const float*)d_in[3];
    const float* att_src  = (const float*)d_in[4];
    const float* att_dst  = (const float*)d_in[5];
    const float* gbias    = (const float*)d_in[6];
    const float* prelu_a  = (const float*)d_in[7];
    float* out = (float*)d_out;

    cudaFuncSetAttribute(attn_kernel,
                         cudaFuncAttributeMaxDynamicSharedMemorySize, 70656);

    dim3 g1(4, M_ / 64, D_ / 64);
    proj_kernel<<<g1, 256>>>(x, Wp, bp);
    score_kernel<<<dim3(4, B_), 256>>>(att_src, att_dst);
    attn_kernel<<<dim3(8, ORD, B_), 256, 70656>>>(A, gbias, out);
    final_kernel<<<(B_ * S_ * D_ + 255) / 256, 256>>>(out, prelu_a);
}

// round 5
// speedup vs baseline: 1.9611x; 1.9611x over previous
#include <cuda_runtime.h>
#include <cuda_bf16.h>
#include <cstdint>

#define B_   64
#define ORD  2
#define S_   256
#define D_   256
#define H_   8
#define HD_  32
#define M_   (B_ * S_)

// ---------------- device scratch (allocation-free) ----------------
__device__ float g_xp[4][M_ * D_];            // projected x (+bias), fp32
__device__ float g_as[4][M_ * H_];            // per-source scores
__device__ float g_ad[4][M_ * H_];            // per-dest scores
__device__ __nv_bfloat16 g_xh[2][M_ * D_];    // x split hi  [m][k]
__device__ __nv_bfloat16 g_xl[2][M_ * D_];    // x split lo
__device__ __nv_bfloat16 g_wh[4][D_ * D_];    // W^T split hi [n][k]
__device__ __nv_bfloat16 g_wl[4][D_ * D_];    // W^T split lo
__device__ __nv_bfloat16 g_xvh[4][M_ * D_];   // values transposed hi [(b*H+h)*HD+d][s]
__device__ __nv_bfloat16 g_xvl[4][M_ * D_];   // values transposed lo

// ---------------- HMMA helper ----------------
__device__ __forceinline__ void mma16816(float* c, const uint32_t a0, const uint32_t a1,
                                         const uint32_t a2, const uint32_t a3,
                                         const uint32_t b0, const uint32_t b1) {
    asm volatile(
        "mma.sync.aligned.m16n8k16.row.col.f32.bf16.bf16.f32 "
        "{%0,%1,%2,%3}, {%4,%5,%6,%7}, {%8,%9}, {%0,%1,%2,%3};"
        : "+f"(c[0]), "+f"(c[1]), "+f"(c[2]), "+f"(c[3])
        : "r"(a0), "r"(a1), "r"(a2), "r"(a3), "r"(b0), "r"(b1));
}

// ---------------------------------------------------------------------------
// split-conversion kernels
// ---------------------------------------------------------------------------
__global__ void convert_x_kernel(const float* __restrict__ x) {
    long q = (long)blockIdx.x * 256 + threadIdx.x;   // float4 index
    float4 v = ((const float4*)x)[q];
    long e = q * 4;
    int d = (int)(e & 255);
    long sd = e >> 8;
    int s = (int)(sd & 255);
    int bi = (int)(sd >> 8);
    int i = bi & 1, b = bi >> 1;
    long o = ((long)(b * 256 + s)) * 256 + d;
    union { __nv_bfloat16 h[4]; uint2 u; } ph, pl;
    float f[4] = {v.x, v.y, v.z, v.w};
    #pragma unroll
    for (int t = 0; t < 4; t++) {
        __nv_bfloat16 hi = __float2bfloat16(f[t]);
        ph.h[t] = hi;
        pl.h[t] = __float2bfloat16(f[t] - __bfloat162float(hi));
    }
    *(uint2*)&g_xh[i][o] = ph.u;
    *(uint2*)&g_xl[i][o] = pl.u;
}

__global__ void convert_w_kernel(const float* __restrict__ Wp) {
    int idx = blockIdx.x * 256 + threadIdx.x;   // 4*65536 total
    int ij = idx >> 16;
    int r = idx & 65535;
    int k = r >> 8, n = r & 255;
    float v = Wp[idx];
    __nv_bfloat16 hi = __float2bfloat16(v);
    g_wh[ij][n * 256 + k] = hi;
    g_wl[ij][n * 256 + k] = __float2bfloat16(v - __bfloat162float(hi));
}

// ---------------------------------------------------------------------------
// projection via mma.sync: xp[ij][m0:m0+128, n0:n0+64] = X@W + b
// grid (M/128, D/64, 4), 256 threads (8 warps, 4x2)
// ---------------------------------------------------------------------------
#define LDA_P 40   // padded k-stride (bf16 elems) for proj smem
__global__ void __launch_bounds__(256) proj_mma_kernel(const float* __restrict__ bp) {
    __shared__ __align__(16) __nv_bfloat16 Ah_s[128 * LDA_P];
    __shared__ __align__(16) __nv_bfloat16 Al_s[128 * LDA_P];
    __shared__ __align__(16) __nv_bfloat16 Bh_s[64 * LDA_P];
    __shared__ __align__(16) __nv_bfloat16 Bl_s[64 * LDA_P];

    const int tid = threadIdx.x;
    const int wid = tid >> 5, lane = tid & 31;
    const int wm = wid & 3, wn = wid >> 2;
    const int m0 = blockIdx.x * 128;
    const int n0 = blockIdx.y * 64;
    const int ij = blockIdx.z;
    const int i = ij >> 1;
    const int r4 = lane >> 2, c2 = (lane & 3) * 2;

    const __nv_bfloat16* xh = g_xh[i];
    const __nv_bfloat16* xl = g_xl[i];
    const __nv_bfloat16* wh = g_wh[ij];
    const __nv_bfloat16* wl = g_wl[ij];

    float c[2][4][4] = {};

    for (int kc = 0; kc < 8; kc++) {
        const int k0 = kc * 32;
        __syncthreads();
        // stage A: 128 rows x 32 k (hi & lo)
        #pragma unroll
        for (int r = 0; r < 2; r++) {
            int idx = r * 256 + tid;
            int row = idx >> 2, part = idx & 3;
            long gi = (long)(m0 + row) * 256 + k0 + part * 8;
            int so = row * LDA_P + part * 8;
            *(int4*)&Ah_s[so] = *(const int4*)&xh[gi];
            *(int4*)&Al_s[so] = *(const int4*)&xl[gi];
        }
        // stage B: 64 rows x 32 k
        {
            int row = tid >> 2, part = tid & 3;
            long gi = (long)(n0 + row) * 256 + k0 + part * 8;
            int so = row * LDA_P + part * 8;
            *(int4*)&Bh_s[so] = *(const int4*)&wh[gi];
            *(int4*)&Bl_s[so] = *(const int4*)&wl[gi];
        }
        __syncthreads();

        #pragma unroll
        for (int kt = 0; kt < 2; kt++) {
            const int kk = kt * 16;
            uint32_t ah[2][4], al[2][4], bh[4][2], bl[4][2];
            #pragma unroll
            for (int mt = 0; mt < 2; mt++) {
                int ao = (wm * 32 + mt * 16 + r4) * LDA_P + kk + c2;
                ah[mt][0] = *(const uint32_t*)&Ah_s[ao];
                ah[mt][1] = *(const uint32_t*)&Ah_s[ao + 8 * LDA_P];
                ah[mt][2] = *(const uint32_t*)&Ah_s[ao + 8];
                ah[mt][3] = *(const uint32_t*)&Ah_s[ao + 8 * LDA_P + 8];
                al[mt][0] = *(const uint32_t*)&Al_s[ao];
                al[mt][1] = *(const uint32_t*)&Al_s[ao + 8 * LDA_P];
                al[mt][2] = *(const uint32_t*)&Al_s[ao + 8];
                al[mt][3] = *(const uint32_t*)&Al_s[ao + 8 * LDA_P + 8];
            }
            #pragma unroll
            for (int nt = 0; nt < 4; nt++) {
                int bo = (wn * 32 + nt * 8 + r4) * LDA_P + kk + c2;
                bh[nt][0] = *(const uint32_t*)&Bh_s[bo];
                bh[nt][1] = *(const uint32_t*)&Bh_s[bo + 8];
                bl[nt][0] = *(const uint32_t*)&Bl_s[bo];
                bl[nt][1] = *(const uint32_t*)&Bl_s[bo + 8];
            }
            #pragma unroll
            for (int mt = 0; mt < 2; mt++)
                #pragma unroll
                for (int nt = 0; nt < 4; nt++) {
                    mma16816(c[mt][nt], ah[mt][0], ah[mt][1], ah[mt][2], ah[mt][3],
                             bh[nt][0], bh[nt][1]);
                    mma16816(c[mt][nt], ah[mt][0], ah[mt][1], ah[mt][2], ah[mt][3],
                             bl[nt][0], bl[nt][1]);
                    mma16816(c[mt][nt], al[mt][0], al[mt][1], al[mt][2], al[mt][3],
                             bh[nt][0], bh[nt][1]);
                }
        }
    }

    // epilogue: + bias, store fp32
    float* xp = g_xp[ij];
    #pragma unroll
    for (int mt = 0; mt < 2; mt++) {
        int m = m0 + wm * 32 + mt * 16 + r4;
        #pragma unroll
        for (int nt = 0; nt < 4; nt++) {
            int n = n0 + wn * 32 + nt * 8 + c2;
            float2 bb = *(const float2*)&bp[ij * 256 + n];
            float2 o0, o1;
            o0.x = c[mt][nt][0] + bb.x;
            o0.y = c[mt][nt][1] + bb.y;
            o1.x = c[mt][nt][2] + bb.x;
            o1.y = c[mt][nt][3] + bb.y;
            *(float2*)&xp[(long)m * 256 + n]       = o0;
            *(float2*)&xp[(long)(m + 8) * 256 + n] = o1;
        }
    }
}

// ---------------------------------------------------------------------------
// post kernel: per (ij,b): transpose g_xp -> g_xvh/g_xvl [d][s] bf16, and
// compute per-head src/dst scores. grid (4, 64), 256 threads.
// ---------------------------------------------------------------------------
__global__ void post_kernel(const float* __restrict__ att_src,
                            const float* __restrict__ att_dst) {
    __shared__ float tile[32 * 33];
    const int ij = blockIdx.x;
    const int b  = blockIdx.y;
    const int tid = threadIdx.x;
    const int w = tid >> 5, lane = tid & 31;
    const float* xp = g_xp[ij] + (long)b * 256 * 256;

    for (int h = 0; h < 8; h++) {
        float asw = att_src[ij * 256 + h * 32 + lane];
        float adw = att_dst[ij * 256 + h * 32 + lane];
        for (int sc = 0; sc < 8; sc++) {
            __syncthreads();
            {   // load [32 s][32 d] slab
                int sr = tid >> 3, dq = tid & 7;
                float4 v = *(const float4*)&xp[(long)(sc * 32 + sr) * 256 + h * 32 + dq * 4];
                tile[sr * 33 + dq * 4 + 0] = v.x;
                tile[sr * 33 + dq * 4 + 1] = v.y;
                tile[sr * 33 + dq * 4 + 2] = v.z;
                tile[sr * 33 + dq * 4 + 3] = v.w;
            }
            __syncthreads();
            // scores: warp w handles s rows w*4..w*4+3, lane = d
            #pragma unroll
            for (int q = 0; q < 4; q++) {
                int sl = w * 4 + q;
                float v = tile[sl * 33 + lane];
                float ds = v * asw, dd = v * adw;
                #pragma unroll
                for (int o = 16; o > 0; o >>= 1) {
                    ds += __shfl_xor_sync(0xffffffffu, ds, o);
                    dd += __shfl_xor_sync(0xffffffffu, dd, o);
                }
                if (lane == 0) {
                    int s = sc * 32 + sl;
                    g_as[ij][((long)b * 256 + s) * 8 + h] = ds;
                    g_ad[ij][((long)b * 256 + s) * 8 + h] = dd;
                }
            }
            // transposed bf16 hi/lo write: warp w handles d rows w*4..w*4+3, lane = s
            #pragma unroll
            for (int q = 0; q < 4; q++) {
                int d = w * 4 + q;
                float f = tile[lane * 33 + d];
                __nv_bfloat16 hi = __float2bfloat16(f);
                __nv_bfloat16 lo = __float2bfloat16(f - __bfloat162float(hi));
                long o = ((long)((b * 8 + h) * 32 + d)) * 256 + sc * 32 + lane;
                g_xvh[ij][o] = hi;
                g_xvl[ij][o] = lo;
            }
        }
    }
}

// ---------------------------------------------------------------------------
// attention: mask -> leaky -> softmax (SIMT) -> AV via mma.sync bf16 split
// grid (8 t-tiles, ORD, B), 256 threads. dynamic smem 72704 B.
// ---------------------------------------------------------------------------
#define LDA_A 264  // padded s-stride (bf16 elems)
#define O_WH  0
#define O_WL  16896
#define O_XH  33792
#define O_XL  50688
#define O_AS  67584
#define O_AD  68608
#define O_MSK 70656
#define A_TOTAL 72704

__global__ void __launch_bounds__(256) attn_kernel(const int* __restrict__ A,
                            const float* __restrict__ gbias,
                            float* __restrict__ out) {
    const int t0 = blockIdx.x * 32;
    const int i  = blockIdx.y;
    const int b  = blockIdx.z;
    const int tid = threadIdx.x;
    const int lane = tid & 31, wid = tid >> 5;
    const int r4 = lane >> 2, c2 = (lane & 3) * 2;
    const int mt = wid & 1, nt = wid >> 1;   // warp's C tile: t rows mt*16, d cols nt*8

    extern __shared__ __align__(16) char smc[];
    __nv_bfloat16* Wh = (__nv_bfloat16*)(smc + O_WH);
    __nv_bfloat16* Wl = (__nv_bfloat16*)(smc + O_WL);
    __nv_bfloat16* Xh = (__nv_bfloat16*)(smc + O_XH);
    __nv_bfloat16* Xl = (__nv_bfloat16*)(smc + O_XL);
    float* as_sm = (float*)(smc + O_AS);
    float* ad_sm = (float*)(smc + O_AD);
    unsigned* mask_sm = (unsigned*)(smc + O_MSK);

    // edge masks (both convs), bit tp = edge(s, t0+tp)
    {
        const int* Abase = A + ((long)(b * ORD + i) * S_) * S_ + t0;
        for (int k = 0; k < 32; k++) {
            int s = wid * 32 + k;
            int a = Abase[s * S_ + lane];
            unsigned m1 = __ballot_sync(0xffffffffu, (a == 2) | (a == 4));
            unsigned m2 = __ballot_sync(0xffffffffu, (a == 3) | (a == 4));
            if (lane == 0) { mask_sm[s] = m1; mask_sm[256 + s] = m2; }
        }
    }
    for (int idx = tid; idx < 512; idx += 256) {
        int j = idx >> 8, rem = idx & 255;
        int tt = rem >> 3, h = rem & 7;
        ad_sm[idx] = g_ad[i * 2 + j][((long)b * 256 + t0 + tt) * 8 + h];
    }
    __syncthreads();

    for (int h = 0; h < 8; h++) {
        float c[4] = {0.f, 0.f, 0.f, 0.f};
        for (int j = 0; j < 2; j++) {
            const int ij = i * 2 + j;
            __syncthreads();
            // stage X values [32 d][256 s] hi/lo
            {
                const __nv_bfloat16* vh = g_xvh[ij] + ((long)(b * 8 + h) * 32) * 256;
                const __nv_bfloat16* vl = g_xvl[ij] + ((long)(b * 8 + h) * 32) * 256;
                for (int q = tid; q < 2048; q += 256) {
                    int sel = q >> 10, rem = q & 1023;
                    int d = rem >> 5, sv = rem & 31;
                    const __nv_bfloat16* src = (sel ? vl : vh) + d * 256 + sv * 8;
                    __nv_bfloat16* dst = (sel ? Xl : Xh) + d * LDA_A + sv * 8;
                    *(int4*)dst = *(const int4*)src;
                }
                as_sm[tid] = g_as[ij][((long)b * 256 + tid) * 8 + h];
            }
            __syncthreads();

            // softmax over source axis; write probs bf16 hi/lo
            const unsigned* msk = mask_sm + j * 256;
            #pragma unroll
            for (int kk = 0; kk < 4; kk++) {
                int tp = wid + kk * 8;
                float adv = ad_sm[j * 256 + tp * 8 + h];
                float v[8];
                float mx = -1e30f;
                #pragma unroll
                for (int r = 0; r < 8; r++) {
                    int s = r * 32 + lane;
                    float a = as_sm[s] + adv;
                    a = a >= 0.f ? a : 0.2f * a;                  // leaky_relu(0.2)
                    float vv = ((msk[s] >> tp) & 1u) ? a : 0.f;   // masked -> 0
                    v[r] = vv;
                    mx = fmaxf(mx, vv);
                }
                #pragma unroll
                for (int o = 16; o > 0; o >>= 1)
                    mx = fmaxf(mx, __shfl_xor_sync(0xffffffffu, mx, o));
                float sum = 0.f;
                #pragma unroll
                for (int r = 0; r < 8; r++) {
                    float e = __expf(v[r] - mx);
                    v[r] = e;
                    sum += e;
                }
                #pragma unroll
                for (int o = 16; o > 0; o >>= 1)
                    sum += __shfl_xor_sync(0xffffffffu, sum, o);
                float inv = 1.0f / sum;
                #pragma unroll
                for (int r = 0; r < 8; r++) {
                    int s = r * 32 + lane;
                    float p = v[r] * inv;
                    __nv_bfloat16 hi = __float2bfloat16(p);
                    Wh[tp * LDA_A + s] = hi;
                    Wl[tp * LDA_A + s] = __float2bfloat16(p - __bfloat162float(hi));
                }
            }
            __syncthreads();

            // AV: C[16t x 8d] += probs[16t x 256s] @ X[256s x 8d], 3 split passes
            #pragma unroll
            for (int kt = 0; kt < 16; kt++) {
                int ao = (mt * 16 + r4) * LDA_A + kt * 16 + c2;
                uint32_t ah0 = *(const uint32_t*)&Wh[ao];
                uint32_t ah1 = *(const uint32_t*)&Wh[ao + 8 * LDA_A];
                uint32_t ah2 = *(const uint32_t*)&Wh[ao + 8];
                uint32_t ah3 = *(const uint32_t*)&Wh[ao + 8 * LDA_A + 8];
                uint32_t al0 = *(const uint32_t*)&Wl[ao];
                uint32_t al1 = *(const uint32_t*)&Wl[ao + 8 * LDA_A];
                uint32_t al2 = *(const uint32_t*)&Wl[ao + 8];
                uint32_t al3 = *(const uint32_t*)&Wl[ao + 8 * LDA_A + 8];
                int bo = (nt * 8 + r4) * LDA_A + kt * 16 + c2;
                uint32_t bh0 = *(const uint32_t*)&Xh[bo];
                uint32_t bh1 = *(const uint32_t*)&Xh[bo + 8];
                uint32_t bl0 = *(const uint32_t*)&Xl[bo];
                uint32_t bl1 = *(const uint32_t*)&Xl[bo + 8];
                mma16816(c, ah0, ah1, ah2, ah3, bh0, bh1);
                mma16816(c, ah0, ah1, ah2, ah3, bl0, bl1);
                mma16816(c, al0, al1, al2, al3, bh0, bh1);
            }
        }
        // epilogue: + residual xp0 + xp1 + gbias(both convs)
        {
            int t = t0 + mt * 16 + r4;
            int dfull = h * 32 + nt * 8 + c2;
            const float* xp0 = g_xp[i * 2 + 0];
            const float* xp1 = g_xp[i * 2 + 1];
            float2 gb0 = *(const float2*)&gbias[(i * 2 + 0) * 256 + dfull];
            float2 gb1 = *(const float2*)&gbias[(i * 2 + 1) * 256 + dfull];
            float gbx = gb0.x + gb1.x, gby = gb0.y + gb1.y;
            long r0 = ((long)b * 256 + t) * 256 + dfull;
            long r1 = ((long)b * 256 + t + 8) * 256 + dfull;
            float2 x00 = *(const float2*)&xp0[r0];
            float2 x01 = *(const float2*)&xp1[r0];
            float2 x10 = *(const float2*)&xp0[r1];
            float2 x11 = *(const float2*)&xp1[r1];
            float2 o0, o1;
            o0.x = c[0] + x00.x + x01.x + gbx;
            o0.y = c[1] + x00.y + x01.y + gby;
            o1.x = c[2] + x10.x + x11.x + gbx;
            o1.y = c[3] + x10.y + x11.y + gby;
            long ob = ((long)(b * ORD + i) * 256 + t) * 256 + dfull;
            *(float2*)&out[ob] = o0;
            *(float2*)&out[ob + 8 * 256] = o1;
        }
    }
}

// ---------------------------------------------------------------------------
// final: out = prelu(h + mean_over_order(h)), in place
// ---------------------------------------------------------------------------
__global__ void final_kernel(float* __restrict__ out,
                             const float* __restrict__ prelu_a) {
    int idx = blockIdx.x * 256 + threadIdx.x;
    if (idx >= B_ * S_ * D_) return;
    int d = idx & 255;
    int bs = idx >> 8;
    int b = bs >> 8, s = bs & 255;
    long i0 = ((long)(b * ORD + 0) * S_ + s) * D_ + d;
    long i1 = ((long)(b * ORD + 1) * S_ + s) * D_ + d;
    float h0 = out[i0];
    float h1 = out[i1];
    float m = 0.5f * (h0 + h1);
    float a = prelu_a[d];
    float o0 = h0 + m, o1 = h1 + m;
    o0 = o0 >= 0.f ? o0 : a * o0;
    o1 = o1 >= 0.f ? o1 : a * o1;
    out[i0] = o0;
    out[i1] = o1;
}

// ---------------------------------------------------------------------------
extern "C" void kernel_launch(void* const* d_in, const int* in_sizes, int n_in,
                              void* d_out, int out_size) {
    const float* x        = (const float*)d_in[0];
    const int*   A        = (const int*)  d_in[1];
    const float* Wp       = (const float*)d_in[2];
    const float* bp       = (const float*)d_in[3];
    const float* att_src  = (const float*)d_in[4];
    const float* att_dst  = (const float*)d_in[5];
    const float* gbias    = (const float*)d_in[6];
    const float* prelu_a  = (const float*)d_in[7];
    float* out = (float*)d_out;

    cudaFuncSetAttribute(attn_kernel,
                         cudaFuncAttributeMaxDynamicSharedMemorySize, A_TOTAL);

    convert_x_kernel<<<(B_ * ORD * S_ * D_ / 4 + 255) / 256, 256>>>(x);
    convert_w_kernel<<<(4 * D_ * D_ + 255) / 256, 256>>>(Wp);
    proj_mma_kernel<<<dim3(M_ / 128, D_ / 64, 4), 256>>>(bp);
    post_kernel<<<dim3(4, B_), 256>>>(att_src, att_dst);
    attn_kernel<<<dim3(8, ORD, B_), 256, A_TOTAL>>>(A, gbias, out);
    final_kernel<<<(B_ * S_ * D_ + 255) / 256, 256>>>(out, prelu_a);
}

// round 7
// speedup vs baseline: 3.3064x; 1.6860x over previous
#include <cuda_runtime.h>
#include <cuda_bf16.h>
#include <cstdint>

#define B_   64
#define ORD  2
#define S_   256
#define D_   256
#define H_   8
#define HD_  32
#define M_   (B_ * S_)

// ---------------- device scratch (allocation-free) ----------------
__device__ float g_xp[4][M_ * D_];            // projected x (+bias), fp32
__device__ float g_as[4][M_ * H_];            // per-source scores
__device__ float g_ad[4][M_ * H_];            // per-dest scores
__device__ __nv_bfloat16 g_xh[2][M_ * D_];    // x split hi  [m][k]
__device__ __nv_bfloat16 g_xl[2][M_ * D_];    // x split lo
__device__ __nv_bfloat16 g_wh[4][D_ * D_];    // W^T split hi [n][k]
__device__ __nv_bfloat16 g_wl[4][D_ * D_];    // W^T split lo
__device__ __nv_bfloat16 g_xvh[4][M_ * D_];   // values transposed hi [(b*H+h)*HD+d][s]
__device__ __nv_bfloat16 g_xvl[4][M_ * D_];   // values transposed lo

// ---------------- helpers ----------------
__device__ __forceinline__ uint32_t smem_u32(const void* p) {
    uint32_t a;
    asm("{ .reg .u64 t; cvta.to.shared.u64 t, %1; cvt.u32.u64 %0, t; }"
        : "=r"(a) : "l"(p));
    return a;
}
__device__ __forceinline__ void mma16816(float* c, const uint32_t a0, const uint32_t a1,
                                         const uint32_t a2, const uint32_t a3,
                                         const uint32_t b0, const uint32_t b1) {
    asm volatile(
        "mma.sync.aligned.m16n8k16.row.col.f32.bf16.bf16.f32 "
        "{%0,%1,%2,%3}, {%4,%5,%6,%7}, {%8,%9}, {%0,%1,%2,%3};"
        : "+f"(c[0]), "+f"(c[1]), "+f"(c[2]), "+f"(c[3])
        : "r"(a0), "r"(a1), "r"(a2), "r"(a3), "r"(b0), "r"(b1));
}
__device__ __forceinline__ void ldsm_x4(uint32_t& r0, uint32_t& r1, uint32_t& r2,
                                        uint32_t& r3, uint32_t addr) {
    asm volatile("ldmatrix.sync.aligned.m8n8.x4.shared.b16 {%0,%1,%2,%3}, [%4];"
                 : "=r"(r0), "=r"(r1), "=r"(r2), "=r"(r3) : "r"(addr));
}
__device__ __forceinline__ void ldsm_x2(uint32_t& r0, uint32_t& r1, uint32_t addr) {
    asm volatile("ldmatrix.sync.aligned.m8n8.x2.shared.b16 {%0,%1}, [%2];"
                 : "=r"(r0), "=r"(r1) : "r"(addr));
}

// ---------------------------------------------------------------------------
// split-conversion kernels
// ---------------------------------------------------------------------------
__global__ void convert_x_kernel(const float* __restrict__ x) {
    long q = (long)blockIdx.x * 256 + threadIdx.x;   // float4 index
    float4 v = ((const float4*)x)[q];
    long e = q * 4;
    int d = (int)(e & 255);
    long sd = e >> 8;
    int s = (int)(sd & 255);
    int bi = (int)(sd >> 8);
    int i = bi & 1, b = bi >> 1;
    long o = ((long)(b * 256 + s)) * 256 + d;
    union { __nv_bfloat16 h[4]; uint2 u; } ph, pl;
    float f[4] = {v.x, v.y, v.z, v.w};
    #pragma unroll
    for (int t = 0; t < 4; t++) {
        __nv_bfloat16 hi = __float2bfloat16(f[t]);
        ph.h[t] = hi;
        pl.h[t] = __float2bfloat16(f[t] - __bfloat162float(hi));
    }
    *(uint2*)&g_xh[i][o] = ph.u;
    *(uint2*)&g_xl[i][o] = pl.u;
}

__global__ void convert_w_kernel(const float* __restrict__ Wp) {
    int idx = blockIdx.x * 256 + threadIdx.x;   // 4*65536 total
    int ij = idx >> 16;
    int r = idx & 65535;
    int k = r >> 8, n = r & 255;
    float v = Wp[idx];
    __nv_bfloat16 hi = __float2bfloat16(v);
    g_wh[ij][n * 256 + k] = hi;
    g_wl[ij][n * 256 + k] = __float2bfloat16(v - __bfloat162float(hi));
}

// ---------------------------------------------------------------------------
// projection via mma.sync + fused scores + transposed value emit
// grid (M/128, D/64, 4), 256 threads (8 warps, wm 0..3 x wn 0..1)
// n-tile (64) == 2 full heads; warp wn owns head h0+wn entirely.
// ---------------------------------------------------------------------------
#define LDA_P 40    // padded k-stride (bf16 elems) for proj smem
#define LDT_P 136   // padded s-stride for transpose stage
__global__ void __launch_bounds__(256) proj_mma_kernel(
        const float* __restrict__ bp,
        const float* __restrict__ att_src,
        const float* __restrict__ att_dst) {
    __shared__ __align__(16) char psm[34816];
    __nv_bfloat16* Ah_s = (__nv_bfloat16*)(psm);            // 128*40
    __nv_bfloat16* Al_s = (__nv_bfloat16*)(psm + 10240);
    __nv_bfloat16* Bh_s = (__nv_bfloat16*)(psm + 20480);    // 64*40
    __nv_bfloat16* Bl_s = (__nv_bfloat16*)(psm + 25600);    // ends 30720
    __nv_bfloat16* Th   = (__nv_bfloat16*)(psm);            // 64*136 reuse
    __nv_bfloat16* Tl   = (__nv_bfloat16*)(psm + 17408);    // ends 34816

    const int tid = threadIdx.x;
    const int wid = tid >> 5, lane = tid & 31;
    const int wm = wid & 3, wn = wid >> 2;
    const int m0 = blockIdx.x * 128;
    const int n0 = blockIdx.y * 64;
    const int ij = blockIdx.z;
    const int i = ij >> 1;
    const int r4 = lane >> 2, c2 = (lane & 3) * 2;
    const int b = m0 >> 8, s0 = m0 & 255;
    const int h0 = n0 >> 5;           // first head in this n-tile
    const int hw = h0 + wn;           // this warp's head

    const __nv_bfloat16* xh = g_xh[i];
    const __nv_bfloat16* xl = g_xl[i];
    const __nv_bfloat16* wh = g_wh[ij];
    const __nv_bfloat16* wl = g_wl[ij];

    // ldmatrix lane addresses
    const uint32_t sb = smem_u32(psm);
    const int tq = lane >> 3, rq = lane & 7;
    uint32_t aA[2], aB[2];
    #pragma unroll
    for (int mt = 0; mt < 2; mt++)
        aA[mt] = sb + ((wm * 32 + mt * 16 + (tq & 1) * 8 + rq) * LDA_P
                       + (tq >> 1) * 8) * 2;
    #pragma unroll
    for (int np = 0; np < 2; np++)
        aB[np] = sb + 20480 + ((wn * 32 + np * 16 + (tq & 1) * 8 + rq) * LDA_P
                               + (tq >> 1) * 8) * 2;

    float c[2][4][4] = {};

    for (int kc = 0; kc < 8; kc++) {
        const int k0 = kc * 32;
        __syncthreads();
        #pragma unroll
        for (int r = 0; r < 2; r++) {
            int idx = r * 256 + tid;
            int row = idx >> 2, part = idx & 3;
            long gi = (long)(m0 + row) * 256 + k0 + part * 8;
            int so = row * LDA_P + part * 8;
            *(int4*)&Ah_s[so] = *(const int4*)&xh[gi];
            *(int4*)&Al_s[so] = *(const int4*)&xl[gi];
        }
        {
            int row = tid >> 2, part = tid & 3;
            long gi = (long)(n0 + row) * 256 + k0 + part * 8;
            int so = row * LDA_P + part * 8;
            *(int4*)&Bh_s[so] = *(const int4*)&wh[gi];
            *(int4*)&Bl_s[so] = *(const int4*)&wl[gi];
        }
        __syncthreads();

        #pragma unroll
        for (int kt = 0; kt < 2; kt++) {
            const uint32_t off = kt * 32;   // 16 elems * 2B
            uint32_t ah[2][4], al[2][4], bh[4][2], bl[4][2];
            #pragma unroll
            for (int mt = 0; mt < 2; mt++) {
                ldsm_x4(ah[mt][0], ah[mt][1], ah[mt][2], ah[mt][3], aA[mt] + off);
                ldsm_x4(al[mt][0], al[mt][1], al[mt][2], al[mt][3], aA[mt] + 10240 + off);
            }
            #pragma unroll
            for (int np = 0; np < 2; np++) {
                ldsm_x4(bh[2 * np][0], bh[2 * np + 1][0],
                        bh[2 * np][1], bh[2 * np + 1][1], aB[np] + off);
                ldsm_x4(bl[2 * np][0], bl[2 * np + 1][0],
                        bl[2 * np][1], bl[2 * np + 1][1], aB[np] + 5120 + off);
            }
            #pragma unroll
            for (int mt = 0; mt < 2; mt++)
                #pragma unroll
                for (int nt = 0; nt < 4; nt++) {
                    mma16816(c[mt][nt], ah[mt][0], ah[mt][1], ah[mt][2], ah[mt][3],
                             bh[nt][0], bh[nt][1]);
                    mma16816(c[mt][nt], ah[mt][0], ah[mt][1], ah[mt][2], ah[mt][3],
                             bl[nt][0], bl[nt][1]);
                    mma16816(c[mt][nt], al[mt][0], al[mt][1], al[mt][2], al[mt][3],
                             bh[nt][0], bh[nt][1]);
                }
        }
    }

    // ---- epilogue: bias, store xp, fused scores, transposed bf16 emit ----
    float asw[4][2], adw[4][2];
    #pragma unroll
    for (int nt = 0; nt < 4; nt++) {
        int n = n0 + wn * 32 + nt * 8 + c2;
        float2 bb = *(const float2*)&bp[ij * 256 + n];
        float2 sw = *(const float2*)&att_src[ij * 256 + n];
        float2 dw = *(const float2*)&att_dst[ij * 256 + n];
        asw[nt][0] = sw.x; asw[nt][1] = sw.y;
        adw[nt][0] = dw.x; adw[nt][1] = dw.y;
        #pragma unroll
        for (int mt = 0; mt < 2; mt++) {
            c[mt][nt][0] += bb.x; c[mt][nt][1] += bb.y;
            c[mt][nt][2] += bb.x; c[mt][nt][3] += bb.y;
        }
    }
    // store fp32 xp
    float* xp = g_xp[ij];
    #pragma unroll
    for (int mt = 0; mt < 2; mt++) {
        int m = m0 + wm * 32 + mt * 16 + r4;
        #pragma unroll
        for (int nt = 0; nt < 4; nt++) {
            int n = n0 + wn * 32 + nt * 8 + c2;
            *(float2*)&xp[(long)m * 256 + n]       = *(float2*)&c[mt][nt][0];
            *(float2*)&xp[(long)(m + 8) * 256 + n] = *(float2*)&c[mt][nt][2];
        }
    }
    // scores: reduce over this warp's 32 cols (= head hw) per C row
    #pragma unroll
    for (int mt = 0; mt < 2; mt++)
        #pragma unroll
        for (int rr = 0; rr < 2; rr++) {
            float vs = 0.f, vd = 0.f;
            #pragma unroll
            for (int nt = 0; nt < 4; nt++) {
                vs += c[mt][nt][rr * 2 + 0] * asw[nt][0]
                    + c[mt][nt][rr * 2 + 1] * asw[nt][1];
                vd += c[mt][nt][rr * 2 + 0] * adw[nt][0]
                    + c[mt][nt][rr * 2 + 1] * adw[nt][1];
            }
            vs += __shfl_xor_sync(0xffffffffu, vs, 1);
            vs += __shfl_xor_sync(0xffffffffu, vs, 2);
            vd += __shfl_xor_sync(0xffffffffu, vd, 1);
            vd += __shfl_xor_sync(0xffffffffu, vd, 2);
            if ((lane & 3) == 0) {
                int m = m0 + wm * 32 + mt * 16 + rr * 8 + r4;
                g_as[ij][(long)m * 8 + hw] = vs;
                g_ad[ij][(long)m * 8 + hw] = vd;
            }
        }
    // transposed bf16 hi/lo via smem stage (reuses A/B buffers)
    __syncthreads();
    #pragma unroll
    for (int mt = 0; mt < 2; mt++)
        #pragma unroll
        for (int nt = 0; nt < 4; nt++)
            #pragma unroll
            for (int rr = 0; rr < 2; rr++)
                #pragma unroll
                for (int cc = 0; cc < 2; cc++) {
                    float v = c[mt][nt][rr * 2 + cc];
                    int dl = wn * 32 + nt * 8 + c2 + cc;
                    int sl = wm * 32 + mt * 16 + rr * 8 + r4;
                    __nv_bfloat16 hi = __float2bfloat16(v);
                    Th[dl * LDT_P + sl] = hi;
                    Tl[dl * LDT_P + sl] = __float2bfloat16(v - __bfloat162float(hi));
                }
    __syncthreads();
    for (int q = tid; q < 1024; q += 256) {
        int row = q >> 4, off = q & 15;          // row = local d (0..63)
        int h = h0 + (row >> 5), d = row & 31;
        long go = ((long)((b * 8 + h) * 32 + d)) * 256 + s0 + off * 8;
        *(int4*)&g_xvh[ij][go] = *(int4*)&Th[row * LDT_P + off * 8];
        *(int4*)&g_xvl[ij][go] = *(int4*)&Tl[row * LDT_P + off * 8];
    }
}

// ---------------------------------------------------------------------------
// attention: mask -> leaky -> softmax (SIMT) -> AV via mma.sync bf16 split
// grid (8 t-tiles, ORD, B), 256 threads. dynamic smem 72704 B.
// ---------------------------------------------------------------------------
#define LDA_A 264  // padded s-stride (bf16 elems)
#define O_WH  0
#define O_WL  16896
#define O_XH  33792
#define O_XL  50688
#define O_AS  67584
#define O_AD  68608
#define O_MSK 70656
#define A_TOTAL 72704

__global__ void __launch_bounds__(256) attn_kernel(const int* __restrict__ A,
                            const float* __restrict__ gbias,
                            float* __restrict__ out) {
    const int t0 = blockIdx.x * 32;
    const int i  = blockIdx.y;
    const int b  = blockIdx.z;
    const int tid = threadIdx.x;
    const int lane = tid & 31, wid = tid >> 5;
    const int r4 = lane >> 2, c2 = (lane & 3) * 2;
    const int mt = wid & 1, nt = wid >> 1;   // C tile: t rows mt*16, d cols nt*8

    extern __shared__ __align__(16) char smc[];
    __nv_bfloat16* Wh = (__nv_bfloat16*)(smc + O_WH);
    __nv_bfloat16* Wl = (__nv_bfloat16*)(smc + O_WL);
    __nv_bfloat16* Xh = (__nv_bfloat16*)(smc + O_XH);
    __nv_bfloat16* Xl = (__nv_bfloat16*)(smc + O_XL);
    float* as_sm = (float*)(smc + O_AS);
    float* ad_sm = (float*)(smc + O_AD);
    unsigned* mask_sm = (unsigned*)(smc + O_MSK);

    // ldmatrix lane addresses
    const uint32_t sb = smem_u32(smc);
    const int tq = lane >> 3, rq = lane & 7;
    const uint32_t aAh = sb + O_WH +
        (uint32_t)((mt * 16 + (tq & 1) * 8 + rq) * LDA_A + (tq >> 1) * 8) * 2;
    const uint32_t aBh = sb + O_XH +
        (uint32_t)((nt * 8 + rq) * LDA_A + ((lane >> 3) & 1) * 8) * 2;

    // edge masks (both convs), bit tp = edge(s, t0+tp)
    {
        const int* Abase = A + ((long)(b * ORD + i) * S_) * S_ + t0;
        for (int k = 0; k < 32; k++) {
            int s = wid * 32 + k;
            int a = Abase[s * S_ + lane];
            unsigned m1 = __ballot_sync(0xffffffffu, (a == 2) | (a == 4));
            unsigned m2 = __ballot_sync(0xffffffffu, (a == 3) | (a == 4));
            if (lane == 0) { mask_sm[s] = m1; mask_sm[256 + s] = m2; }
        }
    }
    for (int idx = tid; idx < 512; idx += 256) {
        int j = idx >> 8, rem = idx & 255;
        int tt = rem >> 3, h = rem & 7;
        ad_sm[idx] = g_ad[i * 2 + j][((long)b * 256 + t0 + tt) * 8 + h];
    }
    __syncthreads();

    for (int h = 0; h < 8; h++) {
        float c[4] = {0.f, 0.f, 0.f, 0.f};
        for (int j = 0; j < 2; j++) {
            const int ij = i * 2 + j;
            __syncthreads();
            // stage X values [32 d][256 s] hi/lo
            {
                const __nv_bfloat16* vh = g_xvh[ij] + ((long)(b * 8 + h) * 32) * 256;
                const __nv_bfloat16* vl = g_xvl[ij] + ((long)(b * 8 + h) * 32) * 256;
                for (int q = tid; q < 2048; q += 256) {
                    int sel = q >> 10, rem = q & 1023;
                    int d = rem >> 5, sv = rem & 31;
                    const __nv_bfloat16* src = (sel ? vl : vh) + d * 256 + sv * 8;
                    __nv_bfloat16* dst = (sel ? Xl : Xh) + d * LDA_A + sv * 8;
                    *(int4*)dst = *(const int4*)src;
                }
                as_sm[tid] = g_as[ij][((long)b * 256 + tid) * 8 + h];
            }
            __syncthreads();

            // softmax over source axis; write probs bf16 hi/lo
            const unsigned* msk = mask_sm + j * 256;
            #pragma unroll
            for (int kk = 0; kk < 4; kk++) {
                int tp = wid + kk * 8;
                float adv = ad_sm[j * 256 + tp * 8 + h];
                float v[8];
                float mx = -1e30f;
                #pragma unroll
                for (int r = 0; r < 8; r++) {
                    int s = r * 32 + lane;
                    float a = as_sm[s] + adv;
                    a = a >= 0.f ? a : 0.2f * a;                  // leaky_relu(0.2)
                    float vv = ((msk[s] >> tp) & 1u) ? a : 0.f;   // masked -> 0
                    v[r] = vv;
                    mx = fmaxf(mx, vv);
                }
                #pragma unroll
                for (int o = 16; o > 0; o >>= 1)
                    mx = fmaxf(mx, __shfl_xor_sync(0xffffffffu, mx, o));
                float sum = 0.f;
                #pragma unroll
                for (int r = 0; r < 8; r++) {
                    float e = __expf(v[r] - mx);
                    v[r] = e;
                    sum += e;
                }
                #pragma unroll
                for (int o = 16; o > 0; o >>= 1)
                    sum += __shfl_xor_sync(0xffffffffu, sum, o);
                float inv = 1.0f / sum;
                #pragma unroll
                for (int r = 0; r < 8; r++) {
                    int s = r * 32 + lane;
                    float p = v[r] * inv;
                    __nv_bfloat16 hi = __float2bfloat16(p);
                    Wh[tp * LDA_A + s] = hi;
                    Wl[tp * LDA_A + s] = __float2bfloat16(p - __bfloat162float(hi));
                }
            }
            __syncthreads();

            // AV: C[16t x 8d] += probs[16t x 256s] @ X[256s x 8d], 3 split passes
            #pragma unroll
            for (int kt = 0; kt < 16; kt++) {
                const uint32_t off = kt * 32;   // 16 elems * 2B
                uint32_t ah0, ah1, ah2, ah3, al0, al1, al2, al3;
                uint32_t bh0, bh1, bl0, bl1;
                ldsm_x4(ah0, ah1, ah2, ah3, aAh + off);
                ldsm_x4(al0, al1, al2, al3, aAh + (O_WL - O_WH) + off);
                ldsm_x2(bh0, bh1, aBh + off);
                ldsm_x2(bl0, bl1, aBh + (O_XL - O_XH) + off);
                mma16816(c, ah0, ah1, ah2, ah3, bh0, bh1);
                mma16816(c, ah0, ah1, ah2, ah3, bl0, bl1);
                mma16816(c, al0, al1, al2, al3, bh0, bh1);
            }
        }
        // epilogue: + residual xp0 + xp1 + gbias(both convs)
        {
            int t = t0 + mt * 16 + r4;
            int dfull = h * 32 + nt * 8 + c2;
            const float* xp0 = g_xp[i * 2 + 0];
            const float* xp1 = g_xp[i * 2 + 1];
            float2 gb0 = *(const float2*)&gbias[(i * 2 + 0) * 256 + dfull];
            float2 gb1 = *(const float2*)&gbias[(i * 2 + 1) * 256 + dfull];
            float gbx = gb0.x + gb1.x, gby = gb0.y + gb1.y;
            long r0 = ((long)b * 256 + t) * 256 + dfull;
            long r1 = ((long)b * 256 + t + 8) * 256 + dfull;
            float2 x00 = *(const float2*)&xp0[r0];
            float2 x01 = *(const float2*)&xp1[r0];
            float2 x10 = *(const float2*)&xp0[r1];
            float2 x11 = *(const float2*)&xp1[r1];
            float2 o0, o1;
            o0.x = c[0] + x00.x + x01.x + gbx;
            o0.y = c[1] + x00.y + x01.y + gby;
            o1.x = c[2] + x10.x + x11.x + gbx;
            o1.y = c[3] + x10.y + x11.y + gby;
            long ob = ((long)(b * ORD + i) * 256 + t) * 256 + dfull;
            *(float2*)&out[ob] = o0;
            *(float2*)&out[ob + 8 * 256] = o1;
        }
    }
}

// ---------------------------------------------------------------------------
// final: out = prelu(h + mean_over_order(h)), in place
// ---------------------------------------------------------------------------
__global__ void final_kernel(float* __restrict__ out,
                             const float* __restrict__ prelu_a) {
    int idx = blockIdx.x * 256 + threadIdx.x;
    if (idx >= B_ * S_ * D_) return;
    int d = idx & 255;
    int bs = idx >> 8;
    int b = bs >> 8, s = bs & 255;
    long i0 = ((long)(b * ORD + 0) * S_ + s) * D_ + d;
    long i1 = ((long)(b * ORD + 1) * S_ + s) * D_ + d;
    float h0 = out[i0];
    float h1 = out[i1];
    float m = 0.5f * (h0 + h1);
    float a = prelu_a[d];
    float o0 = h0 + m, o1 = h1 + m;
    o0 = o0 >= 0.f ? o0 : a * o0;
    o1 = o1 >= 0.f ? o1 : a * o1;
    out[i0] = o0;
    out[i1] = o1;
}

// ---------------------------------------------------------------------------
extern "C" void kernel_launch(void* const* d_in, const int* in_sizes, int n_in,
                              void* d_out, int out_size) {
    const float* x        = (const float*)d_in[0];
    const int*   A        = (const int*)  d_in[1];
    const float* Wp       = (const float*)d_in[2];
    const float* bp       = (const float*)d_in[3];
    const float* att_src  = (const float*)d_in[4];
    const float* att_dst  = (const float*)d_in[5];
    const float* gbias    = (const float*)d_in[6];
    const float* prelu_a  = (const float*)d_in[7];
    float* out = (float*)d_out;

    cudaFuncSetAttribute(attn_kernel,
                         cudaFuncAttributeMaxDynamicSharedMemorySize, A_TOTAL);

    convert_x_kernel<<<(B_ * ORD * S_ * D_ / 4 + 255) / 256, 256>>>(x);
    convert_w_kernel<<<(4 * D_ * D_ + 255) / 256, 256>>>(Wp);
    proj_mma_kernel<<<dim3(M_ / 128, D_ / 64, 4), 256>>>(bp, att_src, att_dst);
    attn_kernel<<<dim3(8, ORD, B_), 256, A_TOTAL>>>(A, gbias, out);
    final_kernel<<<(B_ * S_ * D_ + 255) / 256, 256>>>(out, prelu_a);
}

// round 8
// speedup vs baseline: 3.5331x; 1.0686x over previous
#include <cuda_runtime.h>
#include <cuda_bf16.h>
#include <cstdint>

#define B_   64
#define ORD  2
#define S_   256
#define D_   256
#define H_   8
#define HD_  32
#define M_   (B_ * S_)

// ---------------- device scratch (allocation-free) ----------------
__device__ float g_xp[4][M_ * D_];            // projected x (+bias), fp32
__device__ float g_as[4][M_ * H_];            // per-source scores
__device__ float g_ad[4][M_ * H_];            // per-dest scores
__device__ __nv_bfloat16 g_xh[2][M_ * D_];    // x split hi  [m][k]
__device__ __nv_bfloat16 g_xl[2][M_ * D_];    // x split lo
__device__ __nv_bfloat16 g_wh[4][D_ * D_];    // W^T split hi [n][k]
__device__ __nv_bfloat16 g_wl[4][D_ * D_];    // W^T split lo
__device__ __nv_bfloat16 g_xvh[4][M_ * D_];   // values transposed hi [(b*H+h)*HD+d][s]
__device__ __nv_bfloat16 g_xvl[4][M_ * D_];   // values transposed lo

// ---------------- helpers ----------------
__device__ __forceinline__ uint32_t smem_u32(const void* p) {
    uint32_t a;
    asm("{ .reg .u64 t; cvta.to.shared.u64 t, %1; cvt.u32.u64 %0, t; }"
        : "=r"(a) : "l"(p));
    return a;
}
__device__ __forceinline__ void mma16816(float* c, const uint32_t a0, const uint32_t a1,
                                         const uint32_t a2, const uint32_t a3,
                                         const uint32_t b0, const uint32_t b1) {
    asm volatile(
        "mma.sync.aligned.m16n8k16.row.col.f32.bf16.bf16.f32 "
        "{%0,%1,%2,%3}, {%4,%5,%6,%7}, {%8,%9}, {%0,%1,%2,%3};"
        : "+f"(c[0]), "+f"(c[1]), "+f"(c[2]), "+f"(c[3])
        : "r"(a0), "r"(a1), "r"(a2), "r"(a3), "r"(b0), "r"(b1));
}
__device__ __forceinline__ void ldsm_x4(uint32_t& r0, uint32_t& r1, uint32_t& r2,
                                        uint32_t& r3, uint32_t addr) {
    asm volatile("ldmatrix.sync.aligned.m8n8.x4.shared.b16 {%0,%1,%2,%3}, [%4];"
                 : "=r"(r0), "=r"(r1), "=r"(r2), "=r"(r3) : "r"(addr));
}
__device__ __forceinline__ void ldsm_x2(uint32_t& r0, uint32_t& r1, uint32_t addr) {
    asm volatile("ldmatrix.sync.aligned.m8n8.x2.shared.b16 {%0,%1}, [%2];"
                 : "=r"(r0), "=r"(r1) : "r"(addr));
}

// ---------------------------------------------------------------------------
// split-conversion kernels
// ---------------------------------------------------------------------------
__global__ void convert_x_kernel(const float* __restrict__ x) {
    long q = (long)blockIdx.x * 256 + threadIdx.x;   // float4 index
    float4 v = ((const float4*)x)[q];
    long e = q * 4;
    int d = (int)(e & 255);
    long sd = e >> 8;
    int s = (int)(sd & 255);
    int bi = (int)(sd >> 8);
    int i = bi & 1, b = bi >> 1;
    long o = ((long)(b * 256 + s)) * 256 + d;
    union { __nv_bfloat16 h[4]; uint2 u; } ph, pl;
    float f[4] = {v.x, v.y, v.z, v.w};
    #pragma unroll
    for (int t = 0; t < 4; t++) {
        __nv_bfloat16 hi = __float2bfloat16(f[t]);
        ph.h[t] = hi;
        pl.h[t] = __float2bfloat16(f[t] - __bfloat162float(hi));
    }
    *(uint2*)&g_xh[i][o] = ph.u;
    *(uint2*)&g_xl[i][o] = pl.u;
}

__global__ void convert_w_kernel(const float* __restrict__ Wp) {
    int idx = blockIdx.x * 256 + threadIdx.x;   // 4*65536 total
    int ij = idx >> 16;
    int r = idx & 65535;
    int k = r >> 8, n = r & 255;
    float v = Wp[idx];
    __nv_bfloat16 hi = __float2bfloat16(v);
    g_wh[ij][n * 256 + k] = hi;
    g_wl[ij][n * 256 + k] = __float2bfloat16(v - __bfloat162float(hi));
}

// ---------------------------------------------------------------------------
// projection via mma.sync + fused scores + transposed value emit
// grid (M/128, D/64, 4), 256 threads (8 warps, wm 0..3 x wn 0..1)
// ---------------------------------------------------------------------------
#define LDA_P 40    // padded k-stride (bf16 elems) for proj smem
#define LDT_P 136   // padded s-stride for transpose stage
__global__ void __launch_bounds__(256) proj_mma_kernel(
        const float* __restrict__ bp,
        const float* __restrict__ att_src,
        const float* __restrict__ att_dst) {
    __shared__ __align__(16) char psm[34816];
    __nv_bfloat16* Ah_s = (__nv_bfloat16*)(psm);            // 128*40
    __nv_bfloat16* Al_s = (__nv_bfloat16*)(psm + 10240);
    __nv_bfloat16* Bh_s = (__nv_bfloat16*)(psm + 20480);    // 64*40
    __nv_bfloat16* Bl_s = (__nv_bfloat16*)(psm + 25600);    // ends 30720
    __nv_bfloat16* Th   = (__nv_bfloat16*)(psm);            // 64*136 reuse
    __nv_bfloat16* Tl   = (__nv_bfloat16*)(psm + 17408);    // ends 34816

    const int tid = threadIdx.x;
    const int wid = tid >> 5, lane = tid & 31;
    const int wm = wid & 3, wn = wid >> 2;
    const int m0 = blockIdx.x * 128;
    const int n0 = blockIdx.y * 64;
    const int ij = blockIdx.z;
    const int i = ij >> 1;
    const int r4 = lane >> 2, c2 = (lane & 3) * 2;
    const int b = m0 >> 8, s0 = m0 & 255;
    const int h0 = n0 >> 5;
    const int hw = h0 + wn;

    const __nv_bfloat16* xh = g_xh[i];
    const __nv_bfloat16* xl = g_xl[i];
    const __nv_bfloat16* wh = g_wh[ij];
    const __nv_bfloat16* wl = g_wl[ij];

    const uint32_t sb = smem_u32(psm);
    const int tq = lane >> 3, rq = lane & 7;
    uint32_t aA[2], aB[2];
    #pragma unroll
    for (int mt = 0; mt < 2; mt++)
        aA[mt] = sb + ((wm * 32 + mt * 16 + (tq & 1) * 8 + rq) * LDA_P
                       + (tq >> 1) * 8) * 2;
    #pragma unroll
    for (int np = 0; np < 2; np++)
        aB[np] = sb + 20480 + ((wn * 32 + np * 16 + (tq & 1) * 8 + rq) * LDA_P
                               + (tq >> 1) * 8) * 2;

    float c[2][4][4] = {};

    for (int kc = 0; kc < 8; kc++) {
        const int k0 = kc * 32;
        __syncthreads();
        #pragma unroll
        for (int r = 0; r < 2; r++) {
            int idx = r * 256 + tid;
            int row = idx >> 2, part = idx & 3;
            long gi = (long)(m0 + row) * 256 + k0 + part * 8;
            int so = row * LDA_P + part * 8;
            *(int4*)&Ah_s[so] = *(const int4*)&xh[gi];
            *(int4*)&Al_s[so] = *(const int4*)&xl[gi];
        }
        {
            int row = tid >> 2, part = tid & 3;
            long gi = (long)(n0 + row) * 256 + k0 + part * 8;
            int so = row * LDA_P + part * 8;
            *(int4*)&Bh_s[so] = *(const int4*)&wh[gi];
            *(int4*)&Bl_s[so] = *(const int4*)&wl[gi];
        }
        __syncthreads();

        #pragma unroll
        for (int kt = 0; kt < 2; kt++) {
            const uint32_t off = kt * 32;
            uint32_t ah[2][4], al[2][4], bh[4][2], bl[4][2];
            #pragma unroll
            for (int mt = 0; mt < 2; mt++) {
                ldsm_x4(ah[mt][0], ah[mt][1], ah[mt][2], ah[mt][3], aA[mt] + off);
                ldsm_x4(al[mt][0], al[mt][1], al[mt][2], al[mt][3], aA[mt] + 10240 + off);
            }
            #pragma unroll
            for (int np = 0; np < 2; np++) {
                ldsm_x4(bh[2 * np][0], bh[2 * np + 1][0],
                        bh[2 * np][1], bh[2 * np + 1][1], aB[np] + off);
                ldsm_x4(bl[2 * np][0], bl[2 * np + 1][0],
                        bl[2 * np][1], bl[2 * np + 1][1], aB[np] + 5120 + off);
            }
            #pragma unroll
            for (int mt = 0; mt < 2; mt++)
                #pragma unroll
                for (int nt = 0; nt < 4; nt++) {
                    mma16816(c[mt][nt], ah[mt][0], ah[mt][1], ah[mt][2], ah[mt][3],
                             bh[nt][0], bh[nt][1]);
                    mma16816(c[mt][nt], ah[mt][0], ah[mt][1], ah[mt][2], ah[mt][3],
                             bl[nt][0], bl[nt][1]);
                    mma16816(c[mt][nt], al[mt][0], al[mt][1], al[mt][2], al[mt][3],
                             bh[nt][0], bh[nt][1]);
                }
        }
    }

    // ---- epilogue: bias, store xp, fused scores, transposed bf16 emit ----
    float asw[4][2], adw[4][2];
    #pragma unroll
    for (int nt = 0; nt < 4; nt++) {
        int n = n0 + wn * 32 + nt * 8 + c2;
        float2 bb = *(const float2*)&bp[ij * 256 + n];
        float2 sw = *(const float2*)&att_src[ij * 256 + n];
        float2 dw = *(const float2*)&att_dst[ij * 256 + n];
        asw[nt][0] = sw.x; asw[nt][1] = sw.y;
        adw[nt][0] = dw.x; adw[nt][1] = dw.y;
        #pragma unroll
        for (int mt = 0; mt < 2; mt++) {
            c[mt][nt][0] += bb.x; c[mt][nt][1] += bb.y;
            c[mt][nt][2] += bb.x; c[mt][nt][3] += bb.y;
        }
    }
    float* xp = g_xp[ij];
    #pragma unroll
    for (int mt = 0; mt < 2; mt++) {
        int m = m0 + wm * 32 + mt * 16 + r4;
        #pragma unroll
        for (int nt = 0; nt < 4; nt++) {
            int n = n0 + wn * 32 + nt * 8 + c2;
            *(float2*)&xp[(long)m * 256 + n]       = *(float2*)&c[mt][nt][0];
            *(float2*)&xp[(long)(m + 8) * 256 + n] = *(float2*)&c[mt][nt][2];
        }
    }
    #pragma unroll
    for (int mt = 0; mt < 2; mt++)
        #pragma unroll
        for (int rr = 0; rr < 2; rr++) {
            float vs = 0.f, vd = 0.f;
            #pragma unroll
            for (int nt = 0; nt < 4; nt++) {
                vs += c[mt][nt][rr * 2 + 0] * asw[nt][0]
                    + c[mt][nt][rr * 2 + 1] * asw[nt][1];
                vd += c[mt][nt][rr * 2 + 0] * adw[nt][0]
                    + c[mt][nt][rr * 2 + 1] * adw[nt][1];
            }
            vs += __shfl_xor_sync(0xffffffffu, vs, 1);
            vs += __shfl_xor_sync(0xffffffffu, vs, 2);
            vd += __shfl_xor_sync(0xffffffffu, vd, 1);
            vd += __shfl_xor_sync(0xffffffffu, vd, 2);
            if ((lane & 3) == 0) {
                int m = m0 + wm * 32 + mt * 16 + rr * 8 + r4;
                g_as[ij][(long)m * 8 + hw] = vs;
                g_ad[ij][(long)m * 8 + hw] = vd;
            }
        }
    __syncthreads();
    #pragma unroll
    for (int mt = 0; mt < 2; mt++)
        #pragma unroll
        for (int nt = 0; nt < 4; nt++)
            #pragma unroll
            for (int rr = 0; rr < 2; rr++)
                #pragma unroll
                for (int cc = 0; cc < 2; cc++) {
                    float v = c[mt][nt][rr * 2 + cc];
                    int dl = wn * 32 + nt * 8 + c2 + cc;
                    int sl = wm * 32 + mt * 16 + rr * 8 + r4;
                    __nv_bfloat16 hi = __float2bfloat16(v);
                    Th[dl * LDT_P + sl] = hi;
                    Tl[dl * LDT_P + sl] = __float2bfloat16(v - __bfloat162float(hi));
                }
    __syncthreads();
    for (int q = tid; q < 1024; q += 256) {
        int row = q >> 4, off = q & 15;
        int h = h0 + (row >> 5), d = row & 31;
        long go = ((long)((b * 8 + h) * 32 + d)) * 256 + s0 + off * 8;
        *(int4*)&g_xvh[ij][go] = *(int4*)&Th[row * LDT_P + off * 8];
        *(int4*)&g_xvl[ij][go] = *(int4*)&Tl[row * LDT_P + off * 8];
    }
}

// ---------------------------------------------------------------------------
// attention: mask -> leaky -> exp (no reductions) -> AV + denominator MMA
// grid (8 t-tiles, ORD, B), 256 threads. dynamic smem 72704 B.
// ---------------------------------------------------------------------------
#define LDA_A 264  // padded s-stride (bf16 elems)
#define O_WH  0
#define O_WL  16896
#define O_XH  33792
#define O_XL  50688
#define O_AS  67584
#define O_AD  68608
#define O_MSK 70656
#define A_TOTAL 72704
#define ONES_BF16X2 0x3F803F80u

__global__ void __launch_bounds__(256) attn_kernel(const int* __restrict__ A,
                            const float* __restrict__ gbias,
                            float* __restrict__ out) {
    const int t0 = blockIdx.x * 32;
    const int i  = blockIdx.y;
    const int b  = blockIdx.z;
    const int tid = threadIdx.x;
    const int lane = tid & 31, wid = tid >> 5;
    const int r4 = lane >> 2, c2 = (lane & 3) * 2;
    const int mt = wid & 1, nt = wid >> 1;

    extern __shared__ __align__(16) char smc[];
    __nv_bfloat16* Wh = (__nv_bfloat16*)(smc + O_WH);
    __nv_bfloat16* Wl = (__nv_bfloat16*)(smc + O_WL);
    __nv_bfloat16* Xh = (__nv_bfloat16*)(smc + O_XH);
    __nv_bfloat16* Xl = (__nv_bfloat16*)(smc + O_XL);
    float* as_sm = (float*)(smc + O_AS);
    float* ad_sm = (float*)(smc + O_AD);
    unsigned* mask_sm = (unsigned*)(smc + O_MSK);

    const uint32_t sb = smem_u32(smc);
    const int tq = lane >> 3, rq = lane & 7;
    const uint32_t aAh = sb + O_WH +
        (uint32_t)((mt * 16 + (tq & 1) * 8 + rq) * LDA_A + (tq >> 1) * 8) * 2;
    const uint32_t aBh = sb + O_XH +
        (uint32_t)((nt * 8 + rq) * LDA_A + ((lane >> 3) & 1) * 8) * 2;

    {
        const int* Abase = A + ((long)(b * ORD + i) * S_) * S_ + t0;
        for (int k = 0; k < 32; k++) {
            int s = wid * 32 + k;
            int a = Abase[s * S_ + lane];
            unsigned m1 = __ballot_sync(0xffffffffu, (a == 2) | (a == 4));
            unsigned m2 = __ballot_sync(0xffffffffu, (a == 3) | (a == 4));
            if (lane == 0) { mask_sm[s] = m1; mask_sm[256 + s] = m2; }
        }
    }
    for (int idx = tid; idx < 512; idx += 256) {
        int j = idx >> 8, rem = idx & 255;
        int tt = rem >> 3, h = rem & 7;
        ad_sm[idx] = g_ad[i * 2 + j][((long)b * 256 + t0 + tt) * 8 + h];
    }
    __syncthreads();

    for (int h = 0; h < 8; h++) {
        float cres[4] = {0.f, 0.f, 0.f, 0.f};
        for (int j = 0; j < 2; j++) {
            const int ij = i * 2 + j;
            __syncthreads();
            // stage X values [32 d][256 s] hi/lo
            {
                const __nv_bfloat16* vh = g_xvh[ij] + ((long)(b * 8 + h) * 32) * 256;
                const __nv_bfloat16* vl = g_xvl[ij] + ((long)(b * 8 + h) * 32) * 256;
                for (int q = tid; q < 2048; q += 256) {
                    int sel = q >> 10, rem = q & 1023;
                    int d = rem >> 5, sv = rem & 31;
                    const __nv_bfloat16* src = (sel ? vl : vh) + d * 256 + sv * 8;
                    __nv_bfloat16* dst = (sel ? Xl : Xh) + d * LDA_A + sv * 8;
                    *(int4*)dst = *(const int4*)src;
                }
                as_sm[tid] = g_as[ij][((long)b * 256 + tid) * 8 + h];
            }
            __syncthreads();

            // unnormalized softmax numerators e = exp(leaky(masked)), bf16 hi/lo
            // (no max subtraction: scores bounded ~|a|<30; no lane reductions)
            const unsigned* msk = mask_sm + j * 256;
            #pragma unroll
            for (int kk = 0; kk < 4; kk++) {
                int tp = wid + kk * 8;
                float adv = ad_sm[j * 256 + tp * 8 + h];
                #pragma unroll
                for (int r = 0; r < 8; r++) {
                    int s = r * 32 + lane;
                    float a = as_sm[s] + adv;
                    a = a >= 0.f ? a : 0.2f * a;                  // leaky_relu(0.2)
                    float vv = ((msk[s] >> tp) & 1u) ? a : 0.f;   // masked -> 0
                    float e = __expf(vv);
                    __nv_bfloat16 hi = __float2bfloat16(e);
                    Wh[tp * LDA_A + s] = hi;
                    Wl[tp * LDA_A + s] = __float2bfloat16(e - __bfloat162float(hi));
                }
            }
            __syncthreads();

            // AV + denominator: C[16t x 8d] += e @ X ; den[t] += e @ ones
            float c[4] = {0.f, 0.f, 0.f, 0.f};
            float den[4] = {0.f, 0.f, 0.f, 0.f};
            #pragma unroll
            for (int kt = 0; kt < 16; kt++) {
                const uint32_t off = kt * 32;
                uint32_t ah0, ah1, ah2, ah3, al0, al1, al2, al3;
                uint32_t bh0, bh1, bl0, bl1;
                ldsm_x4(ah0, ah1, ah2, ah3, aAh + off);
                ldsm_x4(al0, al1, al2, al3, aAh + (O_WL - O_WH) + off);
                ldsm_x2(bh0, bh1, aBh + off);
                ldsm_x2(bl0, bl1, aBh + (O_XL - O_XH) + off);
                mma16816(c, ah0, ah1, ah2, ah3, bh0, bh1);
                mma16816(c, ah0, ah1, ah2, ah3, bl0, bl1);
                mma16816(c, al0, al1, al2, al3, bh0, bh1);
                mma16816(den, ah0, ah1, ah2, ah3, ONES_BF16X2, ONES_BF16X2);
                mma16816(den, al0, al1, al2, al3, ONES_BF16X2, ONES_BF16X2);
            }
            float inv0 = __fdividef(1.0f, den[0]);
            float inv1 = __fdividef(1.0f, den[2]);
            cres[0] += c[0] * inv0;
            cres[1] += c[1] * inv0;
            cres[2] += c[2] * inv1;
            cres[3] += c[3] * inv1;
        }
        // epilogue: + residual xp0 + xp1 + gbias(both convs)
        {
            int t = t0 + mt * 16 + r4;
            int dfull = h * 32 + nt * 8 + c2;
            const float* xp0 = g_xp[i * 2 + 0];
            const float* xp1 = g_xp[i * 2 + 1];
            float2 gb0 = *(const float2*)&gbias[(i * 2 + 0) * 256 + dfull];
            float2 gb1 = *(const float2*)&gbias[(i * 2 + 1) * 256 + dfull];
            float gbx = gb0.x + gb1.x, gby = gb0.y + gb1.y;
            long r0 = ((long)b * 256 + t) * 256 + dfull;
            long r1 = ((long)b * 256 + t + 8) * 256 + dfull;
            float2 x00 = *(const float2*)&xp0[r0];
            float2 x01 = *(const float2*)&xp1[r0];
            float2 x10 = *(const float2*)&xp0[r1];
            float2 x11 = *(const float2*)&xp1[r1];
            float2 o0, o1;
            o0.x = cres[0] + x00.x + x01.x + gbx;
            o0.y = cres[1] + x00.y + x01.y + gby;
            o1.x = cres[2] + x10.x + x11.x + gbx;
            o1.y = cres[3] + x10.y + x11.y + gby;
            long ob = ((long)(b * ORD + i) * 256 + t) * 256 + dfull;
            *(float2*)&out[ob] = o0;
            *(float2*)&out[ob + 8 * 256] = o1;
        }
    }
}

// ---------------------------------------------------------------------------
// final: out = prelu(h + mean_over_order(h)), in place
// ---------------------------------------------------------------------------
__global__ void final_kernel(float* __restrict__ out,
                             const float* __restrict__ prelu_a) {
    int idx = blockIdx.x * 256 + threadIdx.x;
    if (idx >= B_ * S_ * D_) return;
    int d = idx & 255;
    int bs = idx >> 8;
    int b = bs >> 8, s = bs & 255;
    long i0 = ((long)(b * ORD + 0) * S_ + s) * D_ + d;
    long i1 = ((long)(b * ORD + 1) * S_ + s) * D_ + d;
    float h0 = out[i0];
    float h1 = out[i1];
    float m = 0.5f * (h0 + h1);
    float a = prelu_a[d];
    float o0 = h0 + m, o1 = h1 + m;
    o0 = o0 >= 0.f ? o0 : a * o0;
    o1 = o1 >= 0.f ? o1 : a * o1;
    out[i0] = o0;
    out[i1] = o1;
}

// ---------------------------------------------------------------------------
extern "C" void kernel_launch(void* const* d_in, const int* in_sizes, int n_in,
                              void* d_out, int out_size) {
    const float* x        = (const float*)d_in[0];
    const int*   A        = (const int*)  d_in[1];
    const float* Wp       = (const float*)d_in[2];
    const float* bp       = (const float*)d_in[3];
    const float* att_src  = (const float*)d_in[4];
    const float* att_dst  = (const float*)d_in[5];
    const float* gbias    = (const float*)d_in[6];
    const float* prelu_a  = (const float*)d_in[7];
    float* out = (float*)d_out;

    cudaFuncSetAttribute(attn_kernel,
                         cudaFuncAttributeMaxDynamicSharedMemorySize, A_TOTAL);

    convert_x_kernel<<<(B_ * ORD * S_ * D_ / 4 + 255) / 256, 256>>>(x);
    convert_w_kernel<<<(4 * D_ * D_ + 255) / 256, 256>>>(Wp);
    proj_mma_kernel<<<dim3(M_ / 128, D_ / 64, 4), 256>>>(bp, att_src, att_dst);
    attn_kernel<<<dim3(8, ORD, B_), 256, A_TOTAL>>>(A, gbias, out);
    final_kernel<<<(B_ * S_ * D_ + 255) / 256, 256>>>(out, prelu_a);
}

// round 10
// speedup vs baseline: 3.7948x; 1.0741x over previous
#include <cuda_runtime.h>
#include <cuda_bf16.h>
#include <cstdint>

#define B_   64
#define ORD  2
#define S_   256
#define D_   256
#define H_   8
#define HD_  32
#define M_   (B_ * S_)

// ---------------- device scratch (allocation-free) ----------------
__device__ float g_xp[4][M_ * D_];            // projected x (+bias), fp32
__device__ float g_as[4][M_ * H_];            // per-source scores
__device__ float g_ad[4][M_ * H_];            // per-dest scores
__device__ __nv_bfloat16 g_xh[2][M_ * D_];    // x split hi  [m][k]
__device__ __nv_bfloat16 g_xl[2][M_ * D_];    // x split lo
__device__ __nv_bfloat16 g_wh[4][D_ * D_];    // W^T split hi [n][k]
__device__ __nv_bfloat16 g_wl[4][D_ * D_];    // W^T split lo
__device__ __nv_bfloat16 g_xvh[4][M_ * D_];   // values transposed hi [(b*H+h)*HD+d][s]
__device__ __nv_bfloat16 g_xvl[4][M_ * D_];   // values transposed lo

// ---------------- helpers ----------------
__device__ __forceinline__ uint32_t smem_u32(const void* p) {
    uint32_t a;
    asm("{ .reg .u64 t; cvta.to.shared.u64 t, %1; cvt.u32.u64 %0, t; }"
        : "=r"(a) : "l"(p));
    return a;
}
__device__ __forceinline__ void mma16816(float* c, const uint32_t a0, const uint32_t a1,
                                         const uint32_t a2, const uint32_t a3,
                                         const uint32_t b0, const uint32_t b1) {
    asm volatile(
        "mma.sync.aligned.m16n8k16.row.col.f32.bf16.bf16.f32 "
        "{%0,%1,%2,%3}, {%4,%5,%6,%7}, {%8,%9}, {%0,%1,%2,%3};"
        : "+f"(c[0]), "+f"(c[1]), "+f"(c[2]), "+f"(c[3])
        : "r"(a0), "r"(a1), "r"(a2), "r"(a3), "r"(b0), "r"(b1));
}
__device__ __forceinline__ void ldsm_x4(uint32_t& r0, uint32_t& r1, uint32_t& r2,
                                        uint32_t& r3, uint32_t addr) {
    asm volatile("ldmatrix.sync.aligned.m8n8.x4.shared.b16 {%0,%1,%2,%3}, [%4];"
                 : "=r"(r0), "=r"(r1), "=r"(r2), "=r"(r3) : "r"(addr));
}
__device__ __forceinline__ void ldsm_x2(uint32_t& r0, uint32_t& r1, uint32_t addr) {
    asm volatile("ldmatrix.sync.aligned.m8n8.x2.shared.b16 {%0,%1}, [%2];"
                 : "=r"(r0), "=r"(r1) : "r"(addr));
}
#define CP_ASYNC16(dst, src) \
    asm volatile("cp.async.ca.shared.global [%0], [%1], 16;" \
                 :: "r"(dst), "l"(src) : "memory")
#define CP_COMMIT() asm volatile("cp.async.commit_group;" ::: "memory")
#define CP_WAIT1() asm volatile("cp.async.wait_group 1;" ::: "memory")
#define CP_WAIT0() asm volatile("cp.async.wait_group 0;" ::: "memory")

// ---------------------------------------------------------------------------
// split-conversion kernels
// ---------------------------------------------------------------------------
__global__ void convert_x_kernel(const float* __restrict__ x) {
    long q = (long)blockIdx.x * 256 + threadIdx.x;   // float4 index
    float4 v = ((const float4*)x)[q];
    long e = q * 4;
    int d = (int)(e & 255);
    long sd = e >> 8;
    int s = (int)(sd & 255);
    int bi = (int)(sd >> 8);
    int i = bi & 1, b = bi >> 1;
    long o = ((long)(b * 256 + s)) * 256 + d;
    union { __nv_bfloat16 h[4]; uint2 u; } ph, pl;
    float f[4] = {v.x, v.y, v.z, v.w};
    #pragma unroll
    for (int t = 0; t < 4; t++) {
        __nv_bfloat16 hi = __float2bfloat16(f[t]);
        ph.h[t] = hi;
        pl.h[t] = __float2bfloat16(f[t] - __bfloat162float(hi));
    }
    *(uint2*)&g_xh[i][o] = ph.u;
    *(uint2*)&g_xl[i][o] = pl.u;
}

__global__ void convert_w_kernel(const float* __restrict__ Wp) {
    int idx = blockIdx.x * 256 + threadIdx.x;   // 4*65536 total
    int ij = idx >> 16;
    int r = idx & 65535;
    int k = r >> 8, n = r & 255;
    float v = Wp[idx];
    __nv_bfloat16 hi = __float2bfloat16(v);
    g_wh[ij][n * 256 + k] = hi;
    g_wl[ij][n * 256 + k] = __float2bfloat16(v - __bfloat162float(hi));
}

// ---------------------------------------------------------------------------
// projection via mma.sync + fused scores + transposed value emit
// grid (M/128, D/64, 4), 256 threads (8 warps, wm 0..3 x wn 0..1)
// ---------------------------------------------------------------------------
#define LDA_P 40    // padded k-stride (bf16 elems) for proj smem
#define LDT_P 136   // padded s-stride for transpose stage
__global__ void __launch_bounds__(256) proj_mma_kernel(
        const float* __restrict__ bp,
        const float* __restrict__ att_src,
        const float* __restrict__ att_dst) {
    __shared__ __align__(16) char psm[34816];
    __nv_bfloat16* Ah_s = (__nv_bfloat16*)(psm);            // 128*40
    __nv_bfloat16* Al_s = (__nv_bfloat16*)(psm + 10240);
    __nv_bfloat16* Bh_s = (__nv_bfloat16*)(psm + 20480);    // 64*40
    __nv_bfloat16* Bl_s = (__nv_bfloat16*)(psm + 25600);    // ends 30720
    __nv_bfloat16* Th   = (__nv_bfloat16*)(psm);            // 64*136 reuse
    __nv_bfloat16* Tl   = (__nv_bfloat16*)(psm + 17408);    // ends 34816

    const int tid = threadIdx.x;
    const int wid = tid >> 5, lane = tid & 31;
    const int wm = wid & 3, wn = wid >> 2;
    const int m0 = blockIdx.x * 128;
    const int n0 = blockIdx.y * 64;
    const int ij = blockIdx.z;
    const int i = ij >> 1;
    const int r4 = lane >> 2, c2 = (lane & 3) * 2;
    const int b = m0 >> 8, s0 = m0 & 255;
    const int h0 = n0 >> 5;
    const int hw = h0 + wn;

    const __nv_bfloat16* xh = g_xh[i];
    const __nv_bfloat16* xl = g_xl[i];
    const __nv_bfloat16* wh = g_wh[ij];
    const __nv_bfloat16* wl = g_wl[ij];

    const uint32_t sb = smem_u32(psm);
    const int tq = lane >> 3, rq = lane & 7;
    uint32_t aA[2], aB[2];
    #pragma unroll
    for (int mt = 0; mt < 2; mt++)
        aA[mt] = sb + ((wm * 32 + mt * 16 + (tq & 1) * 8 + rq) * LDA_P
                       + (tq >> 1) * 8) * 2;
    #pragma unroll
    for (int np = 0; np < 2; np++)
        aB[np] = sb + 20480 + ((wn * 32 + np * 16 + (tq & 1) * 8 + rq) * LDA_P
                               + (tq >> 1) * 8) * 2;

    float c[2][4][4] = {};

    for (int kc = 0; kc < 8; kc++) {
        const int k0 = kc * 32;
        __syncthreads();
        #pragma unroll
        for (int r = 0; r < 2; r++) {
            int idx = r * 256 + tid;
            int row = idx >> 2, part = idx & 3;
            long gi = (long)(m0 + row) * 256 + k0 + part * 8;
            int so = row * LDA_P + part * 8;
            *(int4*)&Ah_s[so] = *(const int4*)&xh[gi];
            *(int4*)&Al_s[so] = *(const int4*)&xl[gi];
        }
        {
            int row = tid >> 2, part = tid & 3;
            long gi = (long)(n0 + row) * 256 + k0 + part * 8;
            int so = row * LDA_P + part * 8;
            *(int4*)&Bh_s[so] = *(const int4*)&wh[gi];
            *(int4*)&Bl_s[so] = *(const int4*)&wl[gi];
        }
        __syncthreads();

        #pragma unroll
        for (int kt = 0; kt < 2; kt++) {
            const uint32_t off = kt * 32;
            uint32_t ah[2][4], al[2][4], bh[4][2], bl[4][2];
            #pragma unroll
            for (int mt = 0; mt < 2; mt++) {
                ldsm_x4(ah[mt][0], ah[mt][1], ah[mt][2], ah[mt][3], aA[mt] + off);
                ldsm_x4(al[mt][0], al[mt][1], al[mt][2], al[mt][3], aA[mt] + 10240 + off);
            }
            #pragma unroll
            for (int np = 0; np < 2; np++) {
                ldsm_x4(bh[2 * np][0], bh[2 * np + 1][0],
                        bh[2 * np][1], bh[2 * np + 1][1], aB[np] + off);
                ldsm_x4(bl[2 * np][0], bl[2 * np + 1][0],
                        bl[2 * np][1], bl[2 * np + 1][1], aB[np] + 5120 + off);
            }
            #pragma unroll
            for (int mt = 0; mt < 2; mt++)
                #pragma unroll
                for (int nt = 0; nt < 4; nt++) {
                    mma16816(c[mt][nt], ah[mt][0], ah[mt][1], ah[mt][2], ah[mt][3],
                             bh[nt][0], bh[nt][1]);
                    mma16816(c[mt][nt], ah[mt][0], ah[mt][1], ah[mt][2], ah[mt][3],
                             bl[nt][0], bl[nt][1]);
                    mma16816(c[mt][nt], al[mt][0], al[mt][1], al[mt][2], al[mt][3],
                             bh[nt][0], bh[nt][1]);
                }
        }
    }

    // ---- epilogue: bias, store xp, fused scores, transposed bf16 emit ----
    float asw[4][2], adw[4][2];
    #pragma unroll
    for (int nt = 0; nt < 4; nt++) {
        int n = n0 + wn * 32 + nt * 8 + c2;
        float2 bb = *(const float2*)&bp[ij * 256 + n];
        float2 sw = *(const float2*)&att_src[ij * 256 + n];
        float2 dw = *(const float2*)&att_dst[ij * 256 + n];
        asw[nt][0] = sw.x; asw[nt][1] = sw.y;
        adw[nt][0] = dw.x; adw[nt][1] = dw.y;
        #pragma unroll
        for (int mt = 0; mt < 2; mt++) {
            c[mt][nt][0] += bb.x; c[mt][nt][1] += bb.y;
            c[mt][nt][2] += bb.x; c[mt][nt][3] += bb.y;
        }
    }
    float* xp = g_xp[ij];
    #pragma unroll
    for (int mt = 0; mt < 2; mt++) {
        int m = m0 + wm * 32 + mt * 16 + r4;
        #pragma unroll
        for (int nt = 0; nt < 4; nt++) {
            int n = n0 + wn * 32 + nt * 8 + c2;
            *(float2*)&xp[(long)m * 256 + n]       = *(float2*)&c[mt][nt][0];
            *(float2*)&xp[(long)(m + 8) * 256 + n] = *(float2*)&c[mt][nt][2];
        }
    }
    #pragma unroll
    for (int mt = 0; mt < 2; mt++)
        #pragma unroll
        for (int rr = 0; rr < 2; rr++) {
            float vs = 0.f, vd = 0.f;
            #pragma unroll
            for (int nt = 0; nt < 4; nt++) {
                vs += c[mt][nt][rr * 2 + 0] * asw[nt][0]
                    + c[mt][nt][rr * 2 + 1] * asw[nt][1];
                vd += c[mt][nt][rr * 2 + 0] * adw[nt][0]
                    + c[mt][nt][rr * 2 + 1] * adw[nt][1];
            }
            vs += __shfl_xor_sync(0xffffffffu, vs, 1);
            vs += __shfl_xor_sync(0xffffffffu, vs, 2);
            vd += __shfl_xor_sync(0xffffffffu, vd, 1);
            vd += __shfl_xor_sync(0xffffffffu, vd, 2);
            if ((lane & 3) == 0) {
                int m = m0 + wm * 32 + mt * 16 + rr * 8 + r4;
                g_as[ij][(long)m * 8 + hw] = vs;
                g_ad[ij][(long)m * 8 + hw] = vd;
            }
        }
    __syncthreads();
    #pragma unroll
    for (int mt = 0; mt < 2; mt++)
        #pragma unroll
        for (int nt = 0; nt < 4; nt++)
            #pragma unroll
            for (int rr = 0; rr < 2; rr++)
                #pragma unroll
                for (int cc = 0; cc < 2; cc++) {
                    float v = c[mt][nt][rr * 2 + cc];
                    int dl = wn * 32 + nt * 8 + c2 + cc;
                    int sl = wm * 32 + mt * 16 + rr * 8 + r4;
                    __nv_bfloat16 hi = __float2bfloat16(v);
                    Th[dl * LDT_P + sl] = hi;
                    Tl[dl * LDT_P + sl] = __float2bfloat16(v - __bfloat162float(hi));
                }
    __syncthreads();
    for (int q = tid; q < 1024; q += 256) {
        int row = q >> 4, off = q & 15;
        int h = h0 + (row >> 5), d = row & 31;
        long go = ((long)((b * 8 + h) * 32 + d)) * 256 + s0 + off * 8;
        *(int4*)&g_xvh[ij][go] = *(int4*)&Th[row * LDT_P + off * 8];
        *(int4*)&g_xvl[ij][go] = *(int4*)&Tl[row * LDT_P + off * 8];
    }
}

// ---------------------------------------------------------------------------
// attention: mask -> leaky -> exp (vectorized, no reductions) ->
//            AV + denominator MMA; cp.async double-buffered X staging
// grid (8 t-tiles, ORD, B), 256 threads. dynamic smem 108544 B.
// ---------------------------------------------------------------------------
#define LDA_A 264  // padded s-stride (bf16 elems)
#define O_WH   0
#define O_WL   16896
#define O_X    33792   // 2 buffers x (hi 16896 + lo 16896)
#define XBUF   33792
#define O_AS   101376
#define O_AD   102400
#define O_MT   104448  // maskT: [j][tp][w] bit s  (512 words)
#define O_MS   106496  // mask temp: [j][s] bit t' (512 words)
#define A_TOTAL 108544
#define ONES_BF16X2 0x3F803F80u

__global__ void __launch_bounds__(256, 2) attn_kernel(const int* __restrict__ A,
                            const float* __restrict__ gbias,
                            float* __restrict__ out) {
    const int t0 = blockIdx.x * 32;
    const int i  = blockIdx.y;
    const int b  = blockIdx.z;
    const int tid = threadIdx.x;
    const int lane = tid & 31, wid = tid >> 5;
    const int r4 = lane >> 2, c2 = (lane & 3) * 2;
    const int mt = wid & 1, nt = wid >> 1;

    extern __shared__ __align__(16) char smc[];
    __nv_bfloat16* Wh = (__nv_bfloat16*)(smc + O_WH);
    __nv_bfloat16* Wl = (__nv_bfloat16*)(smc + O_WL);
    float* as_sm = (float*)(smc + O_AS);
    float* ad_sm = (float*)(smc + O_AD);
    unsigned* maskT = (unsigned*)(smc + O_MT);
    unsigned* mtmp  = (unsigned*)(smc + O_MS);

    const uint32_t sb = smem_u32(smc);
    const int tq = lane >> 3, rq = lane & 7;
    const uint32_t aAh = sb + O_WH +
        (uint32_t)((mt * 16 + (tq & 1) * 8 + rq) * LDA_A + (tq >> 1) * 8) * 2;
    const uint32_t bOffInRow = (uint32_t)((nt * 8 + rq) * LDA_A + ((lane >> 3) & 1) * 8) * 2;

    // staging geometry for this thread (8 cp.async of 16B per iteration)
    const int sd = tid >> 5 << 0;  // placeholder to keep naming clear
    (void)sd;

    // ---- prologue: start X(h=0,j=0) into buffer 0 ----
    {
        const int ij0 = i * 2;
        #pragma unroll
        for (int r = 0; r < 8; r++) {
            int q = r * 256 + tid;
            int sel = q >> 10, rem = q & 1023;
            int d = rem >> 5, sv = rem & 31;
            const __nv_bfloat16* src =
                (sel ? g_xvl[ij0] : g_xvh[ij0]) + ((long)(b * 8 + 0) * 32 + d) * 256 + sv * 8;
            uint32_t dst = sb + O_X + sel * 16896 + (uint32_t)(d * LDA_A + sv * 8) * 2;
            CP_ASYNC16(dst, src);
        }
        CP_COMMIT();
    }
    float as_next = g_as[i * 2][((long)b * 256 + tid) * 8 + 0];

    // ---- edge masks (both convs): mtmp[j*256+s] bit tp ----
    {
        const int* Abase = A + ((long)(b * ORD + i) * S_) * S_ + t0;
        for (int k = 0; k < 32; k++) {
            int s = wid * 32 + k;
            int a = Abase[s * S_ + lane];
            unsigned m1 = __ballot_sync(0xffffffffu, (a == 2) | (a == 4));
            unsigned m2 = __ballot_sync(0xffffffffu, (a == 3) | (a == 4));
            if (lane == 0) { mtmp[s] = m1; mtmp[256 + s] = m2; }
        }
    }
    for (int idx = tid; idx < 512; idx += 256) {
        int j = idx >> 8, rem = idx & 255;
        int tt = rem >> 3, h = rem & 7;
        ad_sm[idx] = g_ad[i * 2 + j][((long)b * 256 + t0 + tt) * 8 + h];
    }
    __syncthreads();
    // transpose mask bits: maskT[j*256 + tp*8 + w] bit (s&31), s = w*32+lane
    for (int step = 0; step < 64; step++) {
        int word_id = step * 8 + wid;
        int j = word_id >> 8, rem = word_id & 255;
        int tp = rem >> 3, wv = rem & 7;
        unsigned bit = (mtmp[j * 256 + wv * 32 + lane] >> tp) & 1u;
        unsigned w = __ballot_sync(0xffffffffu, bit);
        if (lane == 0) maskT[word_id] = w;
    }
    __syncthreads();
    as_sm[tid] = as_next;
    __syncthreads();

    for (int h = 0; h < 8; h++) {
        float cres[4] = {0.f, 0.f, 0.f, 0.f};
        for (int j = 0; j < 2; j++) {
            const int it = h * 2 + j;
            const int p = it & 1;

            // start next iteration's X staging + as prefetch
            if (it < 15) {
                const int itn = it + 1;
                const int hn = itn >> 1, jn = itn & 1;
                const int ijn = i * 2 + jn;
                uint32_t dbase = sb + O_X + (itn & 1) * XBUF;
                #pragma unroll
                for (int r = 0; r < 8; r++) {
                    int q = r * 256 + tid;
                    int sel = q >> 10, rem = q & 1023;
                    int d = rem >> 5, sv = rem & 31;
                    const __nv_bfloat16* src =
                        (sel ? g_xvl[ijn] : g_xvh[ijn]) + ((long)(b * 8 + hn) * 32 + d) * 256 + sv * 8;
                    uint32_t dst = dbase + sel * 16896 + (uint32_t)(d * LDA_A + sv * 8) * 2;
                    CP_ASYNC16(dst, src);
                }
                CP_COMMIT();
                as_next = g_as[ijn][((long)b * 256 + tid) * 8 + hn];
            }

            // ---- exp loop: 8 consecutive s per lane, 4 tp rows per warp ----
            {
                float4 asA = *(const float4*)&as_sm[lane * 8];
                float4 asB = *(const float4*)&as_sm[lane * 8 + 4];
                float as8[8] = {asA.x, asA.y, asA.z, asA.w, asB.x, asB.y, asB.z, asB.w};
                const int bb = (lane & 3) * 8;
                #pragma unroll
                for (int kk = 0; kk < 4; kk++) {
                    int tp = wid + kk * 8;
                    float adv = ad_sm[j * 256 + tp * 8 + h];
                    unsigned mword = maskT[j * 256 + tp * 8 + (lane >> 2)];
                    float e[8];
                    #pragma unroll
                    for (int r = 0; r < 8; r++) {
                        float a = as8[r] + adv;
                        a = fmaxf(a, 0.2f * a);                       // leaky_relu(0.2)
                        float vv = ((mword >> (bb + r)) & 1u) ? a : 0.f;
                        e[r] = __expf(vv);                            // exp(0)=1 for masked
                    }
                    uint32_t ph[4], pl[4];
                    #pragma unroll
                    for (int pq = 0; pq < 4; pq++) {
                        __nv_bfloat162 h2 = __floats2bfloat162_rn(e[pq * 2], e[pq * 2 + 1]);
                        uint32_t hbits = *(uint32_t*)&h2;
                        ph[pq] = hbits;
                        float f0 = __uint_as_float(hbits << 16);
                        float f1 = __uint_as_float(hbits & 0xFFFF0000u);
                        __nv_bfloat162 l2 = __floats2bfloat162_rn(e[pq * 2] - f0,
                                                                  e[pq * 2 + 1] - f1);
                        pl[pq] = *(uint32_t*)&l2;
                    }
                    *(uint4*)&Wh[tp * LDA_A + lane * 8] = make_uint4(ph[0], ph[1], ph[2], ph[3]);
                    *(uint4*)&Wl[tp * LDA_A + lane * 8] = make_uint4(pl[0], pl[1], pl[2], pl[3]);
                }
            }
            if (it < 15) { CP_WAIT1(); } else { CP_WAIT0(); }
            __syncthreads();

            // ---- AV + denominator ----
            const uint32_t aBh = sb + O_X + p * XBUF + bOffInRow;
            float c[4] = {0.f, 0.f, 0.f, 0.f};
            float den[4] = {0.f, 0.f, 0.f, 0.f};
            #pragma unroll
            for (int kt = 0; kt < 16; kt++) {
                const uint32_t off = kt * 32;
                uint32_t ah0, ah1, ah2, ah3, al0, al1, al2, al3;
                uint32_t bh0, bh1, bl0, bl1;
                ldsm_x4(ah0, ah1, ah2, ah3, aAh + off);
                ldsm_x4(al0, al1, al2, al3, aAh + (O_WL - O_WH) + off);
                ldsm_x2(bh0, bh1, aBh + off);
                ldsm_x2(bl0, bl1, aBh + 16896 + off);
                mma16816(c, ah0, ah1, ah2, ah3, bh0, bh1);
                mma16816(c, ah0, ah1, ah2, ah3, bl0, bl1);
                mma16816(c, al0, al1, al2, al3, bh0, bh1);
                mma16816(den, ah0, ah1, ah2, ah3, ONES_BF16X2, ONES_BF16X2);
                mma16816(den, al0, al1, al2, al3, ONES_BF16X2, ONES_BF16X2);
            }
            float inv0 = __fdividef(1.0f, den[0]);
            float inv1 = __fdividef(1.0f, den[2]);
            cres[0] += c[0] * inv0;
            cres[1] += c[1] * inv0;
            cres[2] += c[2] * inv1;
            cres[3] += c[3] * inv1;

            if (it < 15) as_sm[tid] = as_next;
            __syncthreads();
        }
        // epilogue: + residual xp0 + xp1 + gbias(both convs)
        {
            int t = t0 + mt * 16 + r4;
            int dfull = h * 32 + nt * 8 + c2;
            const float* xp0 = g_xp[i * 2 + 0];
            const float* xp1 = g_xp[i * 2 + 1];
            float2 gb0 = *(const float2*)&gbias[(i * 2 + 0) * 256 + dfull];
            float2 gb1 = *(const float2*)&gbias[(i * 2 + 1) * 256 + dfull];
            float gbx = gb0.x + gb1.x, gby = gb0.y + gb1.y;
            long r0 = ((long)b * 256 + t) * 256 + dfull;
            long r1 = ((long)b * 256 + t + 8) * 256 + dfull;
            float2 x00 = *(const float2*)&xp0[r0];
            float2 x01 = *(const float2*)&xp1[r0];
            float2 x10 = *(const float2*)&xp0[r1];
            float2 x11 = *(const float2*)&xp1[r1];
            float2 o0, o1;
            o0.x = cres[0] + x00.x + x01.x + gbx;
            o0.y = cres[1] + x00.y + x01.y + gby;
            o1.x = cres[2] + x10.x + x11.x + gbx;
            o1.y = cres[3] + x10.y + x11.y + gby;
            long ob = ((long)(b * ORD + i) * 256 + t) * 256 + dfull;
            *(float2*)&out[ob] = o0;
            *(float2*)&out[ob + 8 * 256] = o1;
        }
    }
}

// ---------------------------------------------------------------------------
// final: out = prelu(h + mean_over_order(h)), in place
// ---------------------------------------------------------------------------
__global__ void final_kernel(float* __restrict__ out,
                             const float* __restrict__ prelu_a) {
    int idx = blockIdx.x * 256 + threadIdx.x;
    if (idx >= B_ * S_ * D_) return;
    int d = idx & 255;
    int bs = idx >> 8;
    int b = bs >> 8, s = bs & 255;
    long i0 = ((long)(b * ORD + 0) * S_ + s) * D_ + d;
    long i1 = ((long)(b * ORD + 1) * S_ + s) * D_ + d;
    float h0 = out[i0];
    float h1 = out[i1];
    float m = 0.5f * (h0 + h1);
    float a = prelu_a[d];
    float o0 = h0 + m, o1 = h1 + m;
    o0 = o0 >= 0.f ? o0 : a * o0;
    o1 = o1 >= 0.f ? o1 : a * o1;
    out[i0] = o0;
    out[i1] = o1;
}

// ---------------------------------------------------------------------------
extern "C" void kernel_launch(void* const* d_in, const int* in_sizes, int n_in,
                              void* d_out, int out_size) {
    const float* x        = (const float*)d_in[0];
    const int*   A        = (const int*)  d_in[1];
    const float* Wp       = (const float*)d_in[2];
    const float* bp       = (const float*)d_in[3];
    const float* att_src  = (const float*)d_in[4];
    const float* att_dst  = (const float*)d_in[5];
    const float* gbias    = (const float*)d_in[6];
    const float* prelu_a  = (const float*)d_in[7];
    float* out = (float*)d_out;

    cudaFuncSetAttribute(attn_kernel,
                         cudaFuncAttributeMaxDynamicSharedMemorySize, A_TOTAL);

    convert_x_kernel<<<(B_ * ORD * S_ * D_ / 4 + 255) / 256, 256>>>(x);
    convert_w_kernel<<<(4 * D_ * D_ + 255) / 256, 256>>>(Wp);
    proj_mma_kernel<<<dim3(M_ / 128, D_ / 64, 4), 256>>>(bp, att_src, att_dst);
    attn_kernel<<<dim3(8, ORD, B_), 256, A_TOTAL>>>(A, gbias, out);
    final_kernel<<<(B_ * S_ * D_ + 255) / 256, 256>>>(out, prelu_a);
}

// round 12
// speedup vs baseline: 4.5722x; 1.2049x over previous
#include <cuda_runtime.h>
#include <cuda_bf16.h>
#include <cstdint>

#define B_   64
#define ORD  2
#define S_   256
#define D_   256
#define H_   8
#define HD_  32
#define M_   (B_ * S_)

// ---------------- device scratch (allocation-free) ----------------
__device__ float g_xp[4][M_ * D_];            // projected x (+bias), fp32
__device__ float g_as[4][M_ * H_];            // per-source scores
__device__ float g_ad[4][M_ * H_];            // per-dest scores
__device__ __nv_bfloat16 g_xh[2][M_ * D_];    // x split hi  [m][k]
__device__ __nv_bfloat16 g_xl[2][M_ * D_];    // x split lo
__device__ __nv_bfloat16 g_wh[4][D_ * D_];    // W^T split hi [n][k]
__device__ __nv_bfloat16 g_wl[4][D_ * D_];    // W^T split lo
__device__ __nv_bfloat16 g_xvh[4][M_ * D_];   // values transposed bf16 [(b*H+h)*HD+d][s]

// ---------------- helpers ----------------
__device__ __forceinline__ uint32_t smem_u32(const void* p) {
    uint32_t a;
    asm("{ .reg .u64 t; cvta.to.shared.u64 t, %1; cvt.u32.u64 %0, t; }"
        : "=r"(a) : "l"(p));
    return a;
}
__device__ __forceinline__ void mma16816(float* c, const uint32_t a0, const uint32_t a1,
                                         const uint32_t a2, const uint32_t a3,
                                         const uint32_t b0, const uint32_t b1) {
    asm volatile(
        "mma.sync.aligned.m16n8k16.row.col.f32.bf16.bf16.f32 "
        "{%0,%1,%2,%3}, {%4,%5,%6,%7}, {%8,%9}, {%0,%1,%2,%3};"
        : "+f"(c[0]), "+f"(c[1]), "+f"(c[2]), "+f"(c[3])
        : "r"(a0), "r"(a1), "r"(a2), "r"(a3), "r"(b0), "r"(b1));
}
__device__ __forceinline__ void ldsm_x4(uint32_t& r0, uint32_t& r1, uint32_t& r2,
                                        uint32_t& r3, uint32_t addr) {
    asm volatile("ldmatrix.sync.aligned.m8n8.x4.shared.b16 {%0,%1,%2,%3}, [%4];"
                 : "=r"(r0), "=r"(r1), "=r"(r2), "=r"(r3) : "r"(addr));
}
__device__ __forceinline__ void ldsm_x2(uint32_t& r0, uint32_t& r1, uint32_t addr) {
    asm volatile("ldmatrix.sync.aligned.m8n8.x2.shared.b16 {%0,%1}, [%2];"
                 : "=r"(r0), "=r"(r1) : "r"(addr));
}
#define CP_ASYNC16(dst, src) \
    asm volatile("cp.async.ca.shared.global [%0], [%1], 16;" \
                 :: "r"(dst), "l"(src) : "memory")
#define CP_COMMIT() asm volatile("cp.async.commit_group;" ::: "memory")
#define CP_WAIT1() asm volatile("cp.async.wait_group 1;" ::: "memory")
#define CP_WAIT0() asm volatile("cp.async.wait_group 0;" ::: "memory")

// ---------------------------------------------------------------------------
// split-conversion kernels
// ---------------------------------------------------------------------------
__global__ void convert_x_kernel(const float* __restrict__ x) {
    long q = (long)blockIdx.x * 256 + threadIdx.x;   // float4 index
    float4 v = ((const float4*)x)[q];
    long e = q * 4;
    int d = (int)(e & 255);
    long sd = e >> 8;
    int s = (int)(sd & 255);
    int bi = (int)(sd >> 8);
    int i = bi & 1, b = bi >> 1;
    long o = ((long)(b * 256 + s)) * 256 + d;
    union { __nv_bfloat16 h[4]; uint2 u; } ph, pl;
    float f[4] = {v.x, v.y, v.z, v.w};
    #pragma unroll
    for (int t = 0; t < 4; t++) {
        __nv_bfloat16 hi = __float2bfloat16(f[t]);
        ph.h[t] = hi;
        pl.h[t] = __float2bfloat16(f[t] - __bfloat162float(hi));
    }
    *(uint2*)&g_xh[i][o] = ph.u;
    *(uint2*)&g_xl[i][o] = pl.u;
}

__global__ void convert_w_kernel(const float* __restrict__ Wp) {
    int idx = blockIdx.x * 256 + threadIdx.x;   // 4*65536 total
    int ij = idx >> 16;
    int r = idx & 65535;
    int k = r >> 8, n = r & 255;
    float v = Wp[idx];
    __nv_bfloat16 hi = __float2bfloat16(v);
    g_wh[ij][n * 256 + k] = hi;
    g_wl[ij][n * 256 + k] = __float2bfloat16(v - __bfloat162float(hi));
}

// ---------------------------------------------------------------------------
// projection via mma.sync + fused scores + transposed value emit (bf16)
// grid (M/128, D/64, 4), 256 threads (8 warps, wm 0..3 x wn 0..1)
// ---------------------------------------------------------------------------
#define LDA_P 40    // padded k-stride (bf16 elems) for proj smem
#define LDT_P 136   // padded s-stride for transpose stage
__global__ void __launch_bounds__(256) proj_mma_kernel(
        const float* __restrict__ bp,
        const float* __restrict__ att_src,
        const float* __restrict__ att_dst) {
    __shared__ __align__(16) char psm[30720];
    __nv_bfloat16* Ah_s = (__nv_bfloat16*)(psm);            // 128*40
    __nv_bfloat16* Al_s = (__nv_bfloat16*)(psm + 10240);
    __nv_bfloat16* Bh_s = (__nv_bfloat16*)(psm + 20480);    // 64*40
    __nv_bfloat16* Bl_s = (__nv_bfloat16*)(psm + 25600);    // ends 30720
    __nv_bfloat16* Th   = (__nv_bfloat16*)(psm);            // 64*136 reuse (17408)

    const int tid = threadIdx.x;
    const int wid = tid >> 5, lane = tid & 31;
    const int wm = wid & 3, wn = wid >> 2;
    const int m0 = blockIdx.x * 128;
    const int n0 = blockIdx.y * 64;
    const int ij = blockIdx.z;
    const int i = ij >> 1;
    const int r4 = lane >> 2, c2 = (lane & 3) * 2;
    const int b = m0 >> 8, s0 = m0 & 255;
    const int h0 = n0 >> 5;
    const int hw = h0 + wn;

    const __nv_bfloat16* xh = g_xh[i];
    const __nv_bfloat16* xl = g_xl[i];
    const __nv_bfloat16* wh = g_wh[ij];
    const __nv_bfloat16* wl = g_wl[ij];

    const uint32_t sb = smem_u32(psm);
    const int tq = lane >> 3, rq = lane & 7;
    uint32_t aA[2], aB[2];
    #pragma unroll
    for (int mt = 0; mt < 2; mt++)
        aA[mt] = sb + ((wm * 32 + mt * 16 + (tq & 1) * 8 + rq) * LDA_P
                       + (tq >> 1) * 8) * 2;
    #pragma unroll
    for (int np = 0; np < 2; np++)
        aB[np] = sb + 20480 + ((wn * 32 + np * 16 + (tq & 1) * 8 + rq) * LDA_P
                               + (tq >> 1) * 8) * 2;

    float c[2][4][4] = {};

    for (int kc = 0; kc < 8; kc++) {
        const int k0 = kc * 32;
        __syncthreads();
        #pragma unroll
        for (int r = 0; r < 2; r++) {
            int idx = r * 256 + tid;
            int row = idx >> 2, part = idx & 3;
            long gi = (long)(m0 + row) * 256 + k0 + part * 8;
            int so = row * LDA_P + part * 8;
            *(int4*)&Ah_s[so] = *(const int4*)&xh[gi];
            *(int4*)&Al_s[so] = *(const int4*)&xl[gi];
        }
        {
            int row = tid >> 2, part = tid & 3;
            long gi = (long)(n0 + row) * 256 + k0 + part * 8;
            int so = row * LDA_P + part * 8;
            *(int4*)&Bh_s[so] = *(const int4*)&wh[gi];
            *(int4*)&Bl_s[so] = *(const int4*)&wl[gi];
        }
        __syncthreads();

        #pragma unroll
        for (int kt = 0; kt < 2; kt++) {
            const uint32_t off = kt * 32;
            uint32_t ah[2][4], al[2][4], bh[4][2], bl[4][2];
            #pragma unroll
            for (int mt = 0; mt < 2; mt++) {
                ldsm_x4(ah[mt][0], ah[mt][1], ah[mt][2], ah[mt][3], aA[mt] + off);
                ldsm_x4(al[mt][0], al[mt][1], al[mt][2], al[mt][3], aA[mt] + 10240 + off);
            }
            #pragma unroll
            for (int np = 0; np < 2; np++) {
                ldsm_x4(bh[2 * np][0], bh[2 * np + 1][0],
                        bh[2 * np][1], bh[2 * np + 1][1], aB[np] + off);
                ldsm_x4(bl[2 * np][0], bl[2 * np + 1][0],
                        bl[2 * np][1], bl[2 * np + 1][1], aB[np] + 5120 + off);
            }
            #pragma unroll
            for (int mt = 0; mt < 2; mt++)
                #pragma unroll
                for (int nt = 0; nt < 4; nt++) {
                    mma16816(c[mt][nt], ah[mt][0], ah[mt][1], ah[mt][2], ah[mt][3],
                             bh[nt][0], bh[nt][1]);
                    mma16816(c[mt][nt], ah[mt][0], ah[mt][1], ah[mt][2], ah[mt][3],
                             bl[nt][0], bl[nt][1]);
                    mma16816(c[mt][nt], al[mt][0], al[mt][1], al[mt][2], al[mt][3],
                             bh[nt][0], bh[nt][1]);
                }
        }
    }

    // ---- epilogue: bias, store xp, fused scores, transposed bf16 emit ----
    float asw[4][2], adw[4][2];
    #pragma unroll
    for (int nt = 0; nt < 4; nt++) {
        int n = n0 + wn * 32 + nt * 8 + c2;
        float2 bb = *(const float2*)&bp[ij * 256 + n];
        float2 sw = *(const float2*)&att_src[ij * 256 + n];
        float2 dw = *(const float2*)&att_dst[ij * 256 + n];
        asw[nt][0] = sw.x; asw[nt][1] = sw.y;
        adw[nt][0] = dw.x; adw[nt][1] = dw.y;
        #pragma unroll
        for (int mt = 0; mt < 2; mt++) {
            c[mt][nt][0] += bb.x; c[mt][nt][1] += bb.y;
            c[mt][nt][2] += bb.x; c[mt][nt][3] += bb.y;
        }
    }
    float* xp = g_xp[ij];
    #pragma unroll
    for (int mt = 0; mt < 2; mt++) {
        int m = m0 + wm * 32 + mt * 16 + r4;
        #pragma unroll
        for (int nt = 0; nt < 4; nt++) {
            int n = n0 + wn * 32 + nt * 8 + c2;
            *(float2*)&xp[(long)m * 256 + n]       = *(float2*)&c[mt][nt][0];
            *(float2*)&xp[(long)(m + 8) * 256 + n] = *(float2*)&c[mt][nt][2];
        }
    }
    #pragma unroll
    for (int mt = 0; mt < 2; mt++)
        #pragma unroll
        for (int rr = 0; rr < 2; rr++) {
            float vs = 0.f, vd = 0.f;
            #pragma unroll
            for (int nt = 0; nt < 4; nt++) {
                vs += c[mt][nt][rr * 2 + 0] * asw[nt][0]
                    + c[mt][nt][rr * 2 + 1] * asw[nt][1];
                vd += c[mt][nt][rr * 2 + 0] * adw[nt][0]
                    + c[mt][nt][rr * 2 + 1] * adw[nt][1];
            }
            vs += __shfl_xor_sync(0xffffffffu, vs, 1);
            vs += __shfl_xor_sync(0xffffffffu, vs, 2);
            vd += __shfl_xor_sync(0xffffffffu, vd, 1);
            vd += __shfl_xor_sync(0xffffffffu, vd, 2);
            if ((lane & 3) == 0) {
                int m = m0 + wm * 32 + mt * 16 + rr * 8 + r4;
                g_as[ij][(long)m * 8 + hw] = vs;
                g_ad[ij][(long)m * 8 + hw] = vd;
            }
        }
    __syncthreads();
    #pragma unroll
    for (int mt = 0; mt < 2; mt++)
        #pragma unroll
        for (int nt = 0; nt < 4; nt++)
            #pragma unroll
            for (int rr = 0; rr < 2; rr++)
                #pragma unroll
                for (int cc = 0; cc < 2; cc++) {
                    float v = c[mt][nt][rr * 2 + cc];
                    int dl = wn * 32 + nt * 8 + c2 + cc;
                    int sl = wm * 32 + mt * 16 + rr * 8 + r4;
                    Th[dl * LDT_P + sl] = __float2bfloat16(v);
                }
    __syncthreads();
    for (int q = tid; q < 1024; q += 256) {
        int row = q >> 4, off = q & 15;
        int h = h0 + (row >> 5), d = row & 31;
        long go = ((long)((b * 8 + h) * 32 + d)) * 256 + s0 + off * 8;
        *(int4*)&g_xvh[ij][go] = *(int4*)&Th[row * LDT_P + off * 8];
    }
}

// ---------------------------------------------------------------------------
// attention: mask -> leaky -> exp (vectorized, no reductions) ->
//            AV + denominator MMA; cp.async double-buffered bf16 X staging
// grid (8 t-tiles, ORD, B), 256 threads. dynamic smem 74752 B, 3 CTAs/SM.
// ---------------------------------------------------------------------------
#define LDA_A 264  // padded s-stride (bf16 elems)
#define O_WH   0
#define O_WL   16896
#define O_X    33792   // 2 buffers x hi 16896
#define XBUF   16896
#define O_AS   67584
#define O_AD   68608
#define O_MT   70656   // maskT: [j][tp][w] bit s  (512 words)
#define O_MS   72704   // mask temp: [j][s] bit t' (512 words)
#define A_TOTAL 74752
#define ONES_BF16X2 0x3F803F80u

__global__ void __launch_bounds__(256, 3) attn_kernel(const int* __restrict__ A,
                            const float* __restrict__ gbias,
                            float* __restrict__ out) {
    const int t0 = blockIdx.x * 32;
    const int i  = blockIdx.y;
    const int b  = blockIdx.z;
    const int tid = threadIdx.x;
    const int lane = tid & 31, wid = tid >> 5;
    const int r4 = lane >> 2, c2 = (lane & 3) * 2;
    const int mt = wid & 1, nt = wid >> 1;

    extern __shared__ __align__(16) char smc[];
    __nv_bfloat16* Wh = (__nv_bfloat16*)(smc + O_WH);
    __nv_bfloat16* Wl = (__nv_bfloat16*)(smc + O_WL);
    float* as_sm = (float*)(smc + O_AS);
    float* ad_sm = (float*)(smc + O_AD);
    unsigned* maskT = (unsigned*)(smc + O_MT);
    unsigned* mtmp  = (unsigned*)(smc + O_MS);

    const uint32_t sb = smem_u32(smc);
    const int tq = lane >> 3, rq = lane & 7;
    const uint32_t aAh = sb + O_WH +
        (uint32_t)((mt * 16 + (tq & 1) * 8 + rq) * LDA_A + (tq >> 1) * 8) * 2;
    const uint32_t bOffInRow = (uint32_t)((nt * 8 + rq) * LDA_A + ((lane >> 3) & 1) * 8) * 2;

    // ---- prologue: start X(h=0,j=0) into buffer 0 (4 x 16B per thread) ----
    {
        const int ij0 = i * 2;
        #pragma unroll
        for (int r = 0; r < 4; r++) {
            int q = r * 256 + tid;
            int d = q >> 5, sv = q & 31;
            const __nv_bfloat16* src =
                g_xvh[ij0] + ((long)(b * 8 + 0) * 32 + d) * 256 + sv * 8;
            uint32_t dst = sb + O_X + (uint32_t)(d * LDA_A + sv * 8) * 2;
            CP_ASYNC16(dst, src);
        }
        CP_COMMIT();
    }
    float as_next = g_as[i * 2][((long)b * 256 + tid) * 8 + 0];

    // ---- edge masks (both convs): mtmp[j*256+s] bit tp ----
    {
        const int* Abase = A + ((long)(b * ORD + i) * S_) * S_ + t0;
        for (int k = 0; k < 32; k++) {
            int s = wid * 32 + k;
            int a = Abase[s * S_ + lane];
            unsigned m1 = __ballot_sync(0xffffffffu, (a == 2) | (a == 4));
            unsigned m2 = __ballot_sync(0xffffffffu, (a == 3) | (a == 4));
            if (lane == 0) { mtmp[s] = m1; mtmp[256 + s] = m2; }
        }
    }
    for (int idx = tid; idx < 512; idx += 256) {
        int j = idx >> 8, rem = idx & 255;
        int tt = rem >> 3, h = rem & 7;
        ad_sm[idx] = g_ad[i * 2 + j][((long)b * 256 + t0 + tt) * 8 + h];
    }
    __syncthreads();
    // transpose mask bits: maskT[j*256 + tp*8 + w] bit (s&31), s = w*32+lane
    for (int step = 0; step < 64; step++) {
        int word_id = step * 8 + wid;
        int j = word_id >> 8, rem = word_id & 255;
        int tp = rem >> 3, wv = rem & 7;
        unsigned bit = (mtmp[j * 256 + wv * 32 + lane] >> tp) & 1u;
        unsigned w = __ballot_sync(0xffffffffu, bit);
        if (lane == 0) maskT[word_id] = w;
    }
    __syncthreads();
    as_sm[tid] = as_next;
    __syncthreads();

    for (int h = 0; h < 8; h++) {
        float cres[4] = {0.f, 0.f, 0.f, 0.f};
        for (int j = 0; j < 2; j++) {
            const int it = h * 2 + j;
            const int p = it & 1;

            // start next iteration's X staging + as prefetch
            if (it < 15) {
                const int itn = it + 1;
                const int hn = itn >> 1, jn = itn & 1;
                const int ijn = i * 2 + jn;
                uint32_t dbase = sb + O_X + (itn & 1) * XBUF;
                #pragma unroll
                for (int r = 0; r < 4; r++) {
                    int q = r * 256 + tid;
                    int d = q >> 5, sv = q & 31;
                    const __nv_bfloat16* src =
                        g_xvh[ijn] + ((long)(b * 8 + hn) * 32 + d) * 256 + sv * 8;
                    uint32_t dst = dbase + (uint32_t)(d * LDA_A + sv * 8) * 2;
                    CP_ASYNC16(dst, src);
                }
                CP_COMMIT();
                as_next = g_as[ijn][((long)b * 256 + tid) * 8 + hn];
            }

            // ---- exp loop: 8 consecutive s per lane, 4 tp rows per warp ----
            {
                float4 asA = *(const float4*)&as_sm[lane * 8];
                float4 asB = *(const float4*)&as_sm[lane * 8 + 4];
                float as8[8] = {asA.x, asA.y, asA.z, asA.w, asB.x, asB.y, asB.z, asB.w};
                const int bb = (lane & 3) * 8;
                #pragma unroll
                for (int kk = 0; kk < 4; kk++) {
                    int tp = wid + kk * 8;
                    float adv = ad_sm[j * 256 + tp * 8 + h];
                    unsigned mword = maskT[j * 256 + tp * 8 + (lane >> 2)];
                    float e[8];
                    #pragma unroll
                    for (int r = 0; r < 8; r++) {
                        float a = as8[r] + adv;
                        a = fmaxf(a, 0.2f * a);                       // leaky_relu(0.2)
                        float vv = ((mword >> (bb + r)) & 1u) ? a : 0.f;
                        e[r] = __expf(vv);                            // exp(0)=1 for masked
                    }
                    uint32_t ph[4], pl[4];
                    #pragma unroll
                    for (int pq = 0; pq < 4; pq++) {
                        __nv_bfloat162 h2 = __floats2bfloat162_rn(e[pq * 2], e[pq * 2 + 1]);
                        uint32_t hbits = *(uint32_t*)&h2;
                        ph[pq] = hbits;
                        float f0 = __uint_as_float(hbits << 16);
                        float f1 = __uint_as_float(hbits & 0xFFFF0000u);
                        __nv_bfloat162 l2 = __floats2bfloat162_rn(e[pq * 2] - f0,
                                                                  e[pq * 2 + 1] - f1);
                        pl[pq] = *(uint32_t*)&l2;
                    }
                    *(uint4*)&Wh[tp * LDA_A + lane * 8] = make_uint4(ph[0], ph[1], ph[2], ph[3]);
                    *(uint4*)&Wl[tp * LDA_A + lane * 8] = make_uint4(pl[0], pl[1], pl[2], pl[3]);
                }
            }
            if (it < 15) { CP_WAIT1(); } else { CP_WAIT0(); }
            __syncthreads();

            // ---- AV + denominator: c = (ph+pl)@Xh ; den = (ph+pl)@ones ----
            const uint32_t aBh = sb + O_X + p * XBUF + bOffInRow;
            float c[4] = {0.f, 0.f, 0.f, 0.f};
            float den[4] = {0.f, 0.f, 0.f, 0.f};
            #pragma unroll
            for (int kt = 0; kt < 16; kt++) {
                const uint32_t off = kt * 32;
                uint32_t ah0, ah1, ah2, ah3, al0, al1, al2, al3;
                uint32_t bh0, bh1;
                ldsm_x4(ah0, ah1, ah2, ah3, aAh + off);
                ldsm_x4(al0, al1, al2, al3, aAh + (O_WL - O_WH) + off);
                ldsm_x2(bh0, bh1, aBh + off);
                mma16816(c, ah0, ah1, ah2, ah3, bh0, bh1);
                mma16816(c, al0, al1, al2, al3, bh0, bh1);
                mma16816(den, ah0, ah1, ah2, ah3, ONES_BF16X2, ONES_BF16X2);
                mma16816(den, al0, al1, al2, al3, ONES_BF16X2, ONES_BF16X2);
            }
            float inv0 = __fdividef(1.0f, den[0]);
            float inv1 = __fdividef(1.0f, den[2]);
            cres[0] += c[0] * inv0;
            cres[1] += c[1] * inv0;
            cres[2] += c[2] * inv1;
            cres[3] += c[3] * inv1;

            if (it < 15) as_sm[tid] = as_next;
            __syncthreads();
        }
        // epilogue: + residual xp0 + xp1 + gbias(both convs)
        {
            int t = t0 + mt * 16 + r4;
            int dfull = h * 32 + nt * 8 + c2;
            const float* xp0 = g_xp[i * 2 + 0];
            const float* xp1 = g_xp[i * 2 + 1];
            float2 gb0 = *(const float2*)&gbias[(i * 2 + 0) * 256 + dfull];
            float2 gb1 = *(const float2*)&gbias[(i * 2 + 1) * 256 + dfull];
            float gbx = gb0.x + gb1.x, gby = gb0.y + gb1.y;
            long r0 = ((long)b * 256 + t) * 256 + dfull;
            long r1 = ((long)b * 256 + t + 8) * 256 + dfull;
            float2 x00 = *(const float2*)&xp0[r0];
            float2 x01 = *(const float2*)&xp1[r0];
            float2 x10 = *(const float2*)&xp0[r1];
            float2 x11 = *(const float2*)&xp1[r1];
            float2 o0, o1;
            o0.x = cres[0] + x00.x + x01.x + gbx;
            o0.y = cres[1] + x00.y + x01.y + gby;
            o1.x = cres[2] + x10.x + x11.x + gbx;
            o1.y = cres[3] + x10.y + x11.y + gby;
            long ob = ((long)(b * ORD + i) * 256 + t) * 256 + dfull;
            *(float2*)&out[ob] = o0;
            *(float2*)&out[ob + 8 * 256] = o1;
        }
    }
}

// ---------------------------------------------------------------------------
// final: out = prelu(h + mean_over_order(h)), in place
// ---------------------------------------------------------------------------
__global__ void final_kernel(float* __restrict__ out,
                             const float* __restrict__ prelu_a) {
    int idx = blockIdx.x * 256 + threadIdx.x;
    if (idx >= B_ * S_ * D_) return;
    int d = idx & 255;
    int bs = idx >> 8;
    int b = bs >> 8, s = bs & 255;
    long i0 = ((long)(b * ORD + 0) * S_ + s) * D_ + d;
    long i1 = ((long)(b * ORD + 1) * S_ + s) * D_ + d;
    float h0 = out[i0];
    float h1 = out[i1];
    float m = 0.5f * (h0 + h1);
    float a = prelu_a[d];
    float o0 = h0 + m, o1 = h1 + m;
    o0 = o0 >= 0.f ? o0 : a * o0;
    o1 = o1 >= 0.f ? o1 : a * o1;
    out[i0] = o0;
    out[i1] = o1;
}

// ---------------------------------------------------------------------------
extern "C" void kernel_launch(void* const* d_in, const int* in_sizes, int n_in,
                              void* d_out, int out_size) {
    const float* x        = (const float*)d_in[0];
    const int*   A        = (const int*)  d_in[1];
    const float* Wp       = (const float*)d_in[2];
    const float* bp       = (const float*)d_in[3];
    const float* att_src  = (const float*)d_in[4];
    const float* att_dst  = (const float*)d_in[5];
    const float* gbias    = (const float*)d_in[6];
    const float* prelu_a  = (const float*)d_in[7];
    float* out = (float*)d_out;

    cudaFuncSetAttribute(attn_kernel,
                         cudaFuncAttributeMaxDynamicSharedMemorySize, A_TOTAL);

    convert_x_kernel<<<(B_ * ORD * S_ * D_ / 4 + 255) / 256, 256>>>(x);
    convert_w_kernel<<<(4 * D_ * D_ + 255) / 256, 256>>>(Wp);
    proj_mma_kernel<<<dim3(M_ / 128, D_ / 64, 4), 256>>>(bp, att_src, att_dst);
    attn_kernel<<<dim3(8, ORD, B_), 256, A_TOTAL>>>(A, gbias, out);
    final_kernel<<<(B_ * S_ * D_ + 255) / 256, 256>>>(out, prelu_a);
}

// round 13
// speedup vs baseline: 4.8939x; 1.0703x over previous
#include <cuda_runtime.h>
#include <cuda_bf16.h>
#include <cstdint>

#define B_   64
#define ORD  2
#define S_   256
#define D_   256
#define H_   8
#define HD_  32
#define M_   (B_ * S_)
#define LOG2E 1.44269504088896f

// ---------------- device scratch (allocation-free) ----------------
__device__ float g_xp[4][M_ * D_];            // projected x (+bias), fp32
__device__ float g_as[4][M_ * H_];            // per-source scores (pre-scaled by log2e)
__device__ float g_ad[4][M_ * H_];            // per-dest scores (pre-scaled by log2e)
__device__ __nv_bfloat16 g_xh[2][M_ * D_];    // x split hi  [m][k]
__device__ __nv_bfloat16 g_xl[2][M_ * D_];    // x split lo
__device__ __nv_bfloat16 g_wh[4][D_ * D_];    // W^T split hi [n][k]
__device__ __nv_bfloat16 g_wl[4][D_ * D_];    // W^T split lo
__device__ __nv_bfloat16 g_xvh[4][M_ * D_];   // values transposed bf16 [(b*H+h)*HD+d][s]

// ---------------- helpers ----------------
__device__ __forceinline__ uint32_t smem_u32(const void* p) {
    uint32_t a;
    asm("{ .reg .u64 t; cvta.to.shared.u64 t, %1; cvt.u32.u64 %0, t; }"
        : "=r"(a) : "l"(p));
    return a;
}
__device__ __forceinline__ void mma16816(float* c, const uint32_t a0, const uint32_t a1,
                                         const uint32_t a2, const uint32_t a3,
                                         const uint32_t b0, const uint32_t b1) {
    asm volatile(
        "mma.sync.aligned.m16n8k16.row.col.f32.bf16.bf16.f32 "
        "{%0,%1,%2,%3}, {%4,%5,%6,%7}, {%8,%9}, {%0,%1,%2,%3};"
        : "+f"(c[0]), "+f"(c[1]), "+f"(c[2]), "+f"(c[3])
        : "r"(a0), "r"(a1), "r"(a2), "r"(a3), "r"(b0), "r"(b1));
}
__device__ __forceinline__ void ldsm_x4(uint32_t& r0, uint32_t& r1, uint32_t& r2,
                                        uint32_t& r3, uint32_t addr) {
    asm volatile("ldmatrix.sync.aligned.m8n8.x4.shared.b16 {%0,%1,%2,%3}, [%4];"
                 : "=r"(r0), "=r"(r1), "=r"(r2), "=r"(r3) : "r"(addr));
}
__device__ __forceinline__ void ldsm_x2(uint32_t& r0, uint32_t& r1, uint32_t addr) {
    asm volatile("ldmatrix.sync.aligned.m8n8.x2.shared.b16 {%0,%1}, [%2];"
                 : "=r"(r0), "=r"(r1) : "r"(addr));
}
__device__ __forceinline__ float ex2f(float x) {
    float r;
    asm("ex2.approx.f32 %0, %1;" : "=f"(r) : "f"(x));
    return r;
}
#define CP_ASYNC16(dst, src) \
    asm volatile("cp.async.ca.shared.global [%0], [%1], 16;" \
                 :: "r"(dst), "l"(src) : "memory")
#define CP_COMMIT() asm volatile("cp.async.commit_group;" ::: "memory")
#define CP_WAIT1() asm volatile("cp.async.wait_group 1;" ::: "memory")
#define CP_WAIT0() asm volatile("cp.async.wait_group 0;" ::: "memory")

// ---------------------------------------------------------------------------
// split-conversion kernels
// ---------------------------------------------------------------------------
__global__ void convert_x_kernel(const float* __restrict__ x) {
    long q = (long)blockIdx.x * 256 + threadIdx.x;   // float4 index
    float4 v = ((const float4*)x)[q];
    long e = q * 4;
    int d = (int)(e & 255);
    long sd = e >> 8;
    int s = (int)(sd & 255);
    int bi = (int)(sd >> 8);
    int i = bi & 1, b = bi >> 1;
    long o = ((long)(b * 256 + s)) * 256 + d;
    union { __nv_bfloat16 h[4]; uint2 u; } ph, pl;
    float f[4] = {v.x, v.y, v.z, v.w};
    #pragma unroll
    for (int t = 0; t < 4; t++) {
        __nv_bfloat16 hi = __float2bfloat16(f[t]);
        ph.h[t] = hi;
        pl.h[t] = __float2bfloat16(f[t] - __bfloat162float(hi));
    }
    *(uint2*)&g_xh[i][o] = ph.u;
    *(uint2*)&g_xl[i][o] = pl.u;
}

__global__ void convert_w_kernel(const float* __restrict__ Wp) {
    int idx = blockIdx.x * 256 + threadIdx.x;   // 4*65536 total
    int ij = idx >> 16;
    int r = idx & 65535;
    int k = r >> 8, n = r & 255;
    float v = Wp[idx];
    __nv_bfloat16 hi = __float2bfloat16(v);
    g_wh[ij][n * 256 + k] = hi;
    g_wl[ij][n * 256 + k] = __float2bfloat16(v - __bfloat162float(hi));
}

// ---------------------------------------------------------------------------
// projection via mma.sync, cp.async double-buffered staging,
// + fused scores (pre-scaled by log2e) + transposed value emit (bf16)
// grid (M/128, D/64, 4), 256 threads (8 warps, wm 0..3 x wn 0..1)
// dynamic smem: 2 stages x 30720 B. Stage: Ah 10240 | Al 10240 | Bh 5120 | Bl 5120
// ---------------------------------------------------------------------------
#define LDA_P 40    // padded k-stride (bf16 elems)
#define LDT_P 136   // padded s-stride for transpose stage
#define PSTG  30720
#define P_TOTAL (2 * PSTG)
__global__ void __launch_bounds__(256) proj_mma_kernel(
        const float* __restrict__ bp,
        const float* __restrict__ att_src,
        const float* __restrict__ att_dst) {
    extern __shared__ __align__(16) char psm[];
    __nv_bfloat16* Th = (__nv_bfloat16*)(psm);   // 64*136*2 = 17408 B reuse

    const int tid = threadIdx.x;
    const int wid = tid >> 5, lane = tid & 31;
    const int wm = wid & 3, wn = wid >> 2;
    const int m0 = blockIdx.x * 128;
    const int n0 = blockIdx.y * 64;
    const int ij = blockIdx.z;
    const int i = ij >> 1;
    const int r4 = lane >> 2, c2 = (lane & 3) * 2;
    const int b = m0 >> 8, s0 = m0 & 255;
    const int h0 = n0 >> 5;
    const int hw = h0 + wn;

    const __nv_bfloat16* xh = g_xh[i];
    const __nv_bfloat16* xl = g_xl[i];
    const __nv_bfloat16* wh = g_wh[ij];
    const __nv_bfloat16* wl = g_wl[ij];

    const uint32_t sb = smem_u32(psm);
    const int tq = lane >> 3, rq = lane & 7;
    uint32_t aA0[2], aB0[2];
    #pragma unroll
    for (int mt = 0; mt < 2; mt++)
        aA0[mt] = sb + ((wm * 32 + mt * 16 + (tq & 1) * 8 + rq) * LDA_P
                        + (tq >> 1) * 8) * 2;
    #pragma unroll
    for (int np = 0; np < 2; np++)
        aB0[np] = sb + 20480 + ((wn * 32 + np * 16 + (tq & 1) * 8 + rq) * LDA_P
                                + (tq >> 1) * 8) * 2;

    // staging thread-constant pieces
    const int arow = tid >> 2, apart = tid & 3;       // used with r offset
    const int brow = tid >> 2, bpart = tid & 3;

    float c[2][4][4] = {};

    // prologue: stage kc=0 into buffer 0
    {
        const int k0 = 0;
        #pragma unroll
        for (int r = 0; r < 2; r++) {
            int row = arow + r * 64;
            long gi = (long)(m0 + row) * 256 + k0 + apart * 8;
            uint32_t dst = sb + row * 80 + apart * 16;
            CP_ASYNC16(dst, xh + gi);
            CP_ASYNC16(dst + 10240, xl + gi);
        }
        {
            long gi = (long)(n0 + brow) * 256 + k0 + bpart * 8;
            uint32_t dst = sb + 20480 + brow * 80 + bpart * 16;
            CP_ASYNC16(dst, wh + gi);
            CP_ASYNC16(dst + 5120, wl + gi);
        }
        CP_COMMIT();
    }

    for (int kc = 0; kc < 8; kc++) {
        const uint32_t boff = (kc & 1) * PSTG;
        CP_WAIT0();
        __syncthreads();
        if (kc < 7) {
            const int k0 = (kc + 1) * 32;
            const uint32_t nboff = ((kc + 1) & 1) * PSTG;
            #pragma unroll
            for (int r = 0; r < 2; r++) {
                int row = arow + r * 64;
                long gi = (long)(m0 + row) * 256 + k0 + apart * 8;
                uint32_t dst = sb + nboff + row * 80 + apart * 16;
                CP_ASYNC16(dst, xh + gi);
                CP_ASYNC16(dst + 10240, xl + gi);
            }
            {
                long gi = (long)(n0 + brow) * 256 + k0 + bpart * 8;
                uint32_t dst = sb + nboff + 20480 + brow * 80 + bpart * 16;
                CP_ASYNC16(dst, wh + gi);
                CP_ASYNC16(dst + 5120, wl + gi);
            }
            CP_COMMIT();
        }

        #pragma unroll
        for (int kt = 0; kt < 2; kt++) {
            const uint32_t off = boff + kt * 32;
            uint32_t ah[2][4], al[2][4], bh[4][2], bl[4][2];
            #pragma unroll
            for (int mt = 0; mt < 2; mt++) {
                ldsm_x4(ah[mt][0], ah[mt][1], ah[mt][2], ah[mt][3], aA0[mt] + off);
                ldsm_x4(al[mt][0], al[mt][1], al[mt][2], al[mt][3], aA0[mt] + 10240 + off);
            }
            #pragma unroll
            for (int np = 0; np < 2; np++) {
                ldsm_x4(bh[2 * np][0], bh[2 * np + 1][0],
                        bh[2 * np][1], bh[2 * np + 1][1], aB0[np] + off);
                ldsm_x4(bl[2 * np][0], bl[2 * np + 1][0],
                        bl[2 * np][1], bl[2 * np + 1][1], aB0[np] + 5120 + off);
            }
            #pragma unroll
            for (int mt = 0; mt < 2; mt++)
                #pragma unroll
                for (int nt = 0; nt < 4; nt++) {
                    mma16816(c[mt][nt], ah[mt][0], ah[mt][1], ah[mt][2], ah[mt][3],
                             bh[nt][0], bh[nt][1]);
                    mma16816(c[mt][nt], ah[mt][0], ah[mt][1], ah[mt][2], ah[mt][3],
                             bl[nt][0], bl[nt][1]);
                    mma16816(c[mt][nt], al[mt][0], al[mt][1], al[mt][2], al[mt][3],
                             bh[nt][0], bh[nt][1]);
                }
        }
    }

    // ---- epilogue: bias, store xp, fused scores (x log2e), bf16 transpose ----
    float asw[4][2], adw[4][2];
    #pragma unroll
    for (int nt = 0; nt < 4; nt++) {
        int n = n0 + wn * 32 + nt * 8 + c2;
        float2 bb = *(const float2*)&bp[ij * 256 + n];
        float2 sw = *(const float2*)&att_src[ij * 256 + n];
        float2 dw = *(const float2*)&att_dst[ij * 256 + n];
        asw[nt][0] = sw.x; asw[nt][1] = sw.y;
        adw[nt][0] = dw.x; adw[nt][1] = dw.y;
        #pragma unroll
        for (int mt = 0; mt < 2; mt++) {
            c[mt][nt][0] += bb.x; c[mt][nt][1] += bb.y;
            c[mt][nt][2] += bb.x; c[mt][nt][3] += bb.y;
        }
    }
    float* xp = g_xp[ij];
    #pragma unroll
    for (int mt = 0; mt < 2; mt++) {
        int m = m0 + wm * 32 + mt * 16 + r4;
        #pragma unroll
        for (int nt = 0; nt < 4; nt++) {
            int n = n0 + wn * 32 + nt * 8 + c2;
            *(float2*)&xp[(long)m * 256 + n]       = *(float2*)&c[mt][nt][0];
            *(float2*)&xp[(long)(m + 8) * 256 + n] = *(float2*)&c[mt][nt][2];
        }
    }
    #pragma unroll
    for (int mt = 0; mt < 2; mt++)
        #pragma unroll
        for (int rr = 0; rr < 2; rr++) {
            float vs = 0.f, vd = 0.f;
            #pragma unroll
            for (int nt = 0; nt < 4; nt++) {
                vs += c[mt][nt][rr * 2 + 0] * asw[nt][0]
                    + c[mt][nt][rr * 2 + 1] * asw[nt][1];
                vd += c[mt][nt][rr * 2 + 0] * adw[nt][0]
                    + c[mt][nt][rr * 2 + 1] * adw[nt][1];
            }
            vs += __shfl_xor_sync(0xffffffffu, vs, 1);
            vs += __shfl_xor_sync(0xffffffffu, vs, 2);
            vd += __shfl_xor_sync(0xffffffffu, vd, 1);
            vd += __shfl_xor_sync(0xffffffffu, vd, 2);
            if ((lane & 3) == 0) {
                int m = m0 + wm * 32 + mt * 16 + rr * 8 + r4;
                g_as[ij][(long)m * 8 + hw] = vs * LOG2E;
                g_ad[ij][(long)m * 8 + hw] = vd * LOG2E;
            }
        }
    __syncthreads();
    #pragma unroll
    for (int mt = 0; mt < 2; mt++)
        #pragma unroll
        for (int nt = 0; nt < 4; nt++)
            #pragma unroll
            for (int rr = 0; rr < 2; rr++)
                #pragma unroll
                for (int cc = 0; cc < 2; cc++) {
                    float v = c[mt][nt][rr * 2 + cc];
                    int dl = wn * 32 + nt * 8 + c2 + cc;
                    int sl = wm * 32 + mt * 16 + rr * 8 + r4;
                    Th[dl * LDT_P + sl] = __float2bfloat16(v);
                }
    __syncthreads();
    for (int q = tid; q < 1024; q += 256) {
        int row = q >> 4, off = q & 15;
        int h = h0 + (row >> 5), d = row & 31;
        long go = ((long)((b * 8 + h) * 32 + d)) * 256 + s0 + off * 8;
        *(int4*)&g_xvh[ij][go] = *(int4*)&Th[row * LDT_P + off * 8];
    }
}

// ---------------------------------------------------------------------------
// attention: mask -> leaky -> ex2 (vectorized, no reductions) ->
//            AV + denominator MMA; cp.async double-buffered bf16 X staging
// grid (8 t-tiles, ORD, B), 256 threads. dynamic smem 74752 B, 3 CTAs/SM.
// ---------------------------------------------------------------------------
#define LDA_A 264  // padded s-stride (bf16 elems)
#define O_WH   0
#define O_WL   16896
#define O_X    33792   // 2 buffers x hi 16896
#define XBUF   16896
#define O_AS   67584
#define O_AD   68608
#define O_MT   70656   // maskT: [j][tp][w] bit s  (512 words)
#define O_MS   72704   // mask temp: [j][s] bit t' (512 words)
#define A_TOTAL 74752
#define ONES_BF16X2 0x3F803F80u

__global__ void __launch_bounds__(256, 3) attn_kernel(const int* __restrict__ A,
                            const float* __restrict__ gbias,
                            float* __restrict__ out) {
    const int t0 = blockIdx.x * 32;
    const int i  = blockIdx.y;
    const int b  = blockIdx.z;
    const int tid = threadIdx.x;
    const int lane = tid & 31, wid = tid >> 5;
    const int r4 = lane >> 2, c2 = (lane & 3) * 2;
    const int mt = wid & 1, nt = wid >> 1;

    extern __shared__ __align__(16) char smc[];
    __nv_bfloat16* Wh = (__nv_bfloat16*)(smc + O_WH);
    __nv_bfloat16* Wl = (__nv_bfloat16*)(smc + O_WL);
    float* as_sm = (float*)(smc + O_AS);
    float* ad_sm = (float*)(smc + O_AD);
    unsigned* maskT = (unsigned*)(smc + O_MT);
    unsigned* mtmp  = (unsigned*)(smc + O_MS);

    const uint32_t sb = smem_u32(smc);
    const int tq = lane >> 3, rq = lane & 7;
    const uint32_t aAh = sb + O_WH +
        (uint32_t)((mt * 16 + (tq & 1) * 8 + rq) * LDA_A + (tq >> 1) * 8) * 2;
    const uint32_t bOffInRow = (uint32_t)((nt * 8 + rq) * LDA_A + ((lane >> 3) & 1) * 8) * 2;

    // hoisted staging offsets (thread-constant)
    int soff[4];
    uint32_t doff[4];
    #pragma unroll
    for (int r = 0; r < 4; r++) {
        int q = r * 256 + tid;
        int d = q >> 5, sv = q & 31;
        soff[r] = d * 256 + sv * 8;
        doff[r] = (uint32_t)(d * LDA_A + sv * 8) * 2;
    }
    const __nv_bfloat16* xv0 = g_xvh[i * 2 + 0] + (long)b * 65536;
    const __nv_bfloat16* xv1 = g_xvh[i * 2 + 1] + (long)b * 65536;

    // ---- prologue: start X(h=0,j=0) into buffer 0 (4 x 16B per thread) ----
    {
        #pragma unroll
        for (int r = 0; r < 4; r++)
            CP_ASYNC16(sb + O_X + doff[r], xv0 + soff[r]);
        CP_COMMIT();
    }
    float as_next = g_as[i * 2][((long)b * 256 + tid) * 8 + 0];

    // ---- edge masks (both convs): mtmp[j*256+s] bit tp ----
    {
        const int* Abase = A + ((long)(b * ORD + i) * S_) * S_ + t0;
        for (int k = 0; k < 32; k++) {
            int s = wid * 32 + k;
            int a = Abase[s * S_ + lane];
            unsigned m1 = __ballot_sync(0xffffffffu, (a == 2) | (a == 4));
            unsigned m2 = __ballot_sync(0xffffffffu, (a == 3) | (a == 4));
            if (lane == 0) { mtmp[s] = m1; mtmp[256 + s] = m2; }
        }
    }
    for (int idx = tid; idx < 512; idx += 256) {
        int j = idx >> 8, rem = idx & 255;
        int tt = rem >> 3, h = rem & 7;
        ad_sm[idx] = g_ad[i * 2 + j][((long)b * 256 + t0 + tt) * 8 + h];
    }
    __syncthreads();
    // transpose mask bits: maskT[j*256 + tp*8 + w] bit (s&31), s = w*32+lane
    for (int step = 0; step < 64; step++) {
        int word_id = step * 8 + wid;
        int j = word_id >> 8, rem = word_id & 255;
        int tp = rem >> 3, wv = rem & 7;
        unsigned bit = (mtmp[j * 256 + wv * 32 + lane] >> tp) & 1u;
        unsigned w = __ballot_sync(0xffffffffu, bit);
        if (lane == 0) maskT[word_id] = w;
    }
    __syncthreads();
    as_sm[tid] = as_next;
    __syncthreads();

    for (int h = 0; h < 8; h++) {
        float cres[4] = {0.f, 0.f, 0.f, 0.f};
        for (int j = 0; j < 2; j++) {
            const int it = h * 2 + j;
            const int p = it & 1;

            // start next iteration's X staging + as prefetch
            if (it < 15) {
                const int itn = it + 1;
                const int hn = itn >> 1, jn = itn & 1;
                const __nv_bfloat16* src_base = (jn ? xv1 : xv0) + hn * 8192;
                uint32_t dbase = sb + O_X + (itn & 1) * XBUF;
                #pragma unroll
                for (int r = 0; r < 4; r++)
                    CP_ASYNC16(dbase + doff[r], src_base + soff[r]);
                CP_COMMIT();
                as_next = g_as[i * 2 + jn][((long)b * 256 + tid) * 8 + hn];
            }

            // ---- exp loop: 8 consecutive s per lane, 4 tp rows per warp ----
            {
                float4 asA = *(const float4*)&as_sm[lane * 8];
                float4 asB = *(const float4*)&as_sm[lane * 8 + 4];
                float as8[8] = {asA.x, asA.y, asA.z, asA.w, asB.x, asB.y, asB.z, asB.w};
                const int bb = (lane & 3) * 8;
                #pragma unroll
                for (int kk = 0; kk < 4; kk++) {
                    int tp = wid + kk * 8;
                    float adv = ad_sm[j * 256 + tp * 8 + h];
                    unsigned mword = maskT[j * 256 + tp * 8 + (lane >> 2)];
                    float e[8];
                    #pragma unroll
                    for (int r = 0; r < 8; r++) {
                        float a = as8[r] + adv;
                        a = fmaxf(a, 0.2f * a);                       // leaky_relu(0.2)
                        float vv = ((mword >> (bb + r)) & 1u) ? a : 0.f;
                        e[r] = ex2f(vv);                              // 2^(log2e*x) = exp(x)
                    }
                    uint32_t ph[4], pl[4];
                    #pragma unroll
                    for (int pq = 0; pq < 4; pq++) {
                        __nv_bfloat162 h2 = __floats2bfloat162_rn(e[pq * 2], e[pq * 2 + 1]);
                        uint32_t hbits = *(uint32_t*)&h2;
                        ph[pq] = hbits;
                        float f0 = __uint_as_float(hbits << 16);
                        float f1 = __uint_as_float(hbits & 0xFFFF0000u);
                        __nv_bfloat162 l2 = __floats2bfloat162_rn(e[pq * 2] - f0,
                                                                  e[pq * 2 + 1] - f1);
                        pl[pq] = *(uint32_t*)&l2;
                    }
                    *(uint4*)&Wh[tp * LDA_A + lane * 8] = make_uint4(ph[0], ph[1], ph[2], ph[3]);
                    *(uint4*)&Wl[tp * LDA_A + lane * 8] = make_uint4(pl[0], pl[1], pl[2], pl[3]);
                }
            }
            if (it < 15) { CP_WAIT1(); } else { CP_WAIT0(); }
            __syncthreads();

            // ---- AV + denominator: c = (ph+pl)@Xh ; den = (ph+pl)@ones ----
            const uint32_t aBh = sb + O_X + p * XBUF + bOffInRow;
            float c[4] = {0.f, 0.f, 0.f, 0.f};
            float den[4] = {0.f, 0.f, 0.f, 0.f};
            #pragma unroll
            for (int kt = 0; kt < 16; kt++) {
                const uint32_t off = kt * 32;
                uint32_t ah0, ah1, ah2, ah3, al0, al1, al2, al3;
                uint32_t bh0, bh1;
                ldsm_x4(ah0, ah1, ah2, ah3, aAh + off);
                ldsm_x4(al0, al1, al2, al3, aAh + (O_WL - O_WH) + off);
                ldsm_x2(bh0, bh1, aBh + off);
                mma16816(c, ah0, ah1, ah2, ah3, bh0, bh1);
                mma16816(c, al0, al1, al2, al3, bh0, bh1);
                mma16816(den, ah0, ah1, ah2, ah3, ONES_BF16X2, ONES_BF16X2);
                mma16816(den, al0, al1, al2, al3, ONES_BF16X2, ONES_BF16X2);
            }
            float inv0 = __fdividef(1.0f, den[0]);
            float inv1 = __fdividef(1.0f, den[2]);
            cres[0] += c[0] * inv0;
            cres[1] += c[1] * inv0;
            cres[2] += c[2] * inv1;
            cres[3] += c[3] * inv1;

            if (it < 15) as_sm[tid] = as_next;
            __syncthreads();
        }
        // epilogue: + residual xp0 + xp1 + gbias(both convs)
        {
            int t = t0 + mt * 16 + r4;
            int dfull = h * 32 + nt * 8 + c2;
            const float* xp0 = g_xp[i * 2 + 0];
            const float* xp1 = g_xp[i * 2 + 1];
            float2 gb0 = *(const float2*)&gbias[(i * 2 + 0) * 256 + dfull];
            float2 gb1 = *(const float2*)&gbias[(i * 2 + 1) * 256 + dfull];
            float gbx = gb0.x + gb1.x, gby = gb0.y + gb1.y;
            long r0 = ((long)b * 256 + t) * 256 + dfull;
            long r1 = ((long)b * 256 + t + 8) * 256 + dfull;
            float2 x00 = *(const float2*)&xp0[r0];
            float2 x01 = *(const float2*)&xp1[r0];
            float2 x10 = *(const float2*)&xp0[r1];
            float2 x11 = *(const float2*)&xp1[r1];
            float2 o0, o1;
            o0.x = cres[0] + x00.x + x01.x + gbx;
            o0.y = cres[1] + x00.y + x01.y + gby;
            o1.x = cres[2] + x10.x + x11.x + gbx;
            o1.y = cres[3] + x10.y + x11.y + gby;
            long ob = ((long)(b * ORD + i) * 256 + t) * 256 + dfull;
            *(float2*)&out[ob] = o0;
            *(float2*)&out[ob + 8 * 256] = o1;
        }
    }
}

// ---------------------------------------------------------------------------
// final: out = prelu(h + mean_over_order(h)), in place
// ---------------------------------------------------------------------------
__global__ void final_kernel(float* __restrict__ out,
                             const float* __restrict__ prelu_a) {
    int idx = blockIdx.x * 256 + threadIdx.x;
    if (idx >= B_ * S_ * D_) return;
    int d = idx & 255;
    int bs = idx >> 8;
    int b = bs >> 8, s = bs & 255;
    long i0 = ((long)(b * ORD + 0) * S_ + s) * D_ + d;
    long i1 = ((long)(b * ORD + 1) * S_ + s) * D_ + d;
    float h0 = out[i0];
    float h1 = out[i1];
    float m = 0.5f * (h0 + h1);
    float a = prelu_a[d];
    float o0 = h0 + m, o1 = h1 + m;
    o0 = o0 >= 0.f ? o0 : a * o0;
    o1 = o1 >= 0.f ? o1 : a * o1;
    out[i0] = o0;
    out[i1] = o1;
}

// ---------------------------------------------------------------------------
extern "C" void kernel_launch(void* const* d_in, const int* in_sizes, int n_in,
                              void* d_out, int out_size) {
    const float* x        = (const float*)d_in[0];
    const int*   A        = (const int*)  d_in[1];
    const float* Wp       = (const float*)d_in[2];
    const float* bp       = (const float*)d_in[3];
    const float* att_src  = (const float*)d_in[4];
    const float* att_dst  = (const float*)d_in[5];
    const float* gbias    = (const float*)d_in[6];
    const float* prelu_a  = (const float*)d_in[7];
    float* out = (float*)d_out;

    cudaFuncSetAttribute(attn_kernel,
                         cudaFuncAttributeMaxDynamicSharedMemorySize, A_TOTAL);
    cudaFuncSetAttribute(proj_mma_kernel,
                         cudaFuncAttributeMaxDynamicSharedMemorySize, P_TOTAL);

    convert_x_kernel<<<(B_ * ORD * S_ * D_ / 4 + 255) / 256, 256>>>(x);
    convert_w_kernel<<<(4 * D_ * D_ + 255) / 256, 256>>>(Wp);
    proj_mma_kernel<<<dim3(M_ / 128, D_ / 64, 4), 256, P_TOTAL>>>(bp, att_src, att_dst);
    attn_kernel<<<dim3(8, ORD, B_), 256, A_TOTAL>>>(A, gbias, out);
    final_kernel<<<(B_ * S_ * D_ + 255) / 256, 256>>>(out, prelu_a);
}